// round 1
// baseline (speedup 1.0000x reference)
#include <cuda_runtime.h>
#include <cuda_bf16.h>
#include <math.h>

#define NN 50000
#define NE 500000
#define ET (NE + NN)   /* edges + self loops = 550000 */
#define DIN 128
#define DD 256
#define HH 8
#define CC 32

// ---------------- scratch (static device globals; no allocation) ----------------
__device__ float g_h1[(size_t)NN * DD];   // layer1 GEMM out  [N,256]
__device__ float g_act[(size_t)NN * DD];  // elu(gat1 out)    [N,256]
__device__ float g_h2[(size_t)NN * DD];   // layer2 GEMM out  [N,256]
__device__ float g_es1[NN * HH];
__device__ float g_ed1[NN * HH];
__device__ float g_es2[NN];
__device__ float g_ed2[NN];
__device__ int   g_cnt[NN];
__device__ int   g_off[NN + 1];
__device__ int   g_cur[NN];
__device__ int   g_srcl[ET];

// ---------------- CSR build ----------------
__global__ void k_zero_cnt() {
    int i = blockIdx.x * blockDim.x + threadIdx.x;
    if (i < NN) g_cnt[i] = 0;
}

__global__ void k_count(const int* __restrict__ ei) {
    int t = blockIdx.x * blockDim.x + threadIdx.x;
    if (t >= ET) return;
    int dst = (t < NE) ? ei[NE + t] : (t - NE);
    atomicAdd(&g_cnt[dst], 1);
}

__global__ void k_scan() {
    __shared__ int part[1024];
    const int CH = (NN + 1023) / 1024;  // 49
    int tid = threadIdx.x;
    int start = tid * CH;
    int sum = 0;
    for (int i = 0; i < CH; i++) {
        int idx = start + i;
        if (idx < NN) sum += g_cnt[idx];
    }
    part[tid] = sum;
    __syncthreads();
    for (int d = 1; d < 1024; d <<= 1) {
        int v = (tid >= d) ? part[tid - d] : 0;
        __syncthreads();
        part[tid] += v;
        __syncthreads();
    }
    int run = (tid == 0) ? 0 : part[tid - 1];
    for (int i = 0; i < CH; i++) {
        int idx = start + i;
        if (idx < NN) {
            g_off[idx] = run;
            g_cur[idx] = run;
            run += g_cnt[idx];
        }
    }
    if (tid == 1023) g_off[NN] = run;  // = ET
}

__global__ void k_scatter(const int* __restrict__ ei) {
    int t = blockIdx.x * blockDim.x + threadIdx.x;
    if (t >= ET) return;
    int src, dst;
    if (t < NE) { src = ei[t]; dst = ei[NE + t]; }
    else        { src = t - NE; dst = t - NE; }
    int pos = atomicAdd(&g_cur[dst], 1);
    g_srcl[pos] = src;
}

// ---------------- SGEMM: C[M,256] = A[M,KD] @ B[KD,256] ----------------
// BM=128, BN=128, BK=8, 256 threads, 8x8 microtile.
template <int LAYER, int KD>
__global__ __launch_bounds__(256)
void k_gemm(const float* __restrict__ Ain, const float* __restrict__ B) {
    constexpr int BM = 128, BN = 128, BK = 8;
    const float* A = (LAYER == 1) ? Ain : g_act;
    float* Cc = (LAYER == 1) ? g_h1 : g_h2;

    __shared__ float As[BK][BM + 4];  // +4 keeps float4 rows 16B-aligned (132*4=528, 528%16==0)
    __shared__ float Bs[BK][BN];

    int tid = threadIdx.x;
    int tx = tid & 15, ty = tid >> 4;
    int row0 = blockIdx.y * BM, col0 = blockIdx.x * BN;

    int arow = tid >> 1;          // 0..127
    int acol = (tid & 1) * 4;     // 0 or 4
    int brow = tid >> 5;          // 0..7
    int bcol = (tid & 31) * 4;    // 0..124

    float acc[8][8];
#pragma unroll
    for (int i = 0; i < 8; i++)
#pragma unroll
        for (int j = 0; j < 8; j++) acc[i][j] = 0.f;

    for (int k0 = 0; k0 < KD; k0 += BK) {
        int gr = row0 + arow;
        float4 av = make_float4(0.f, 0.f, 0.f, 0.f);
        if (gr < NN) av = *(const float4*)(A + (size_t)gr * KD + k0 + acol);
        As[acol + 0][arow] = av.x;
        As[acol + 1][arow] = av.y;
        As[acol + 2][arow] = av.z;
        As[acol + 3][arow] = av.w;
        float4 bv = *(const float4*)(B + (size_t)(k0 + brow) * DD + col0 + bcol);
        *(float4*)&Bs[brow][bcol] = bv;
        __syncthreads();
#pragma unroll
        for (int kk = 0; kk < BK; kk++) {
            float a[8], b[8];
            *(float4*)&a[0] = *(const float4*)&As[kk][ty * 8];
            *(float4*)&a[4] = *(const float4*)&As[kk][ty * 8 + 4];
            *(float4*)&b[0] = *(const float4*)&Bs[kk][tx * 8];
            *(float4*)&b[4] = *(const float4*)&Bs[kk][tx * 8 + 4];
#pragma unroll
            for (int i = 0; i < 8; i++)
#pragma unroll
                for (int j = 0; j < 8; j++) acc[i][j] = fmaf(a[i], b[j], acc[i][j]);
        }
        __syncthreads();
    }
#pragma unroll
    for (int i = 0; i < 8; i++) {
        int gr = row0 + ty * 8 + i;
        if (gr < NN) {
            *(float4*)(Cc + (size_t)gr * DD + col0 + tx * 8) =
                make_float4(acc[i][0], acc[i][1], acc[i][2], acc[i][3]);
            *(float4*)(Cc + (size_t)gr * DD + col0 + tx * 8 + 4) =
                make_float4(acc[i][4], acc[i][5], acc[i][6], acc[i][7]);
        }
    }
}

// ---------------- attention coefficients ----------------
// layer1: warp per node, per-head dot over 32 channels
__global__ void k_attn1(const float* __restrict__ a_src, const float* __restrict__ a_dst) {
    int warp = (blockIdx.x * blockDim.x + threadIdx.x) >> 5;
    int lane = threadIdx.x & 31;
    if (warp >= NN) return;
    const float* hrow = g_h1 + (size_t)warp * DD;
    float es[HH], ed[HH];
#pragma unroll
    for (int j = 0; j < HH; j++) {
        float v = hrow[j * CC + lane];
        es[j] = v * a_src[j * CC + lane];
        ed[j] = v * a_dst[j * CC + lane];
    }
#pragma unroll
    for (int off = 16; off; off >>= 1) {
#pragma unroll
        for (int j = 0; j < HH; j++) {
            es[j] += __shfl_xor_sync(0xFFFFFFFFu, es[j], off);
            ed[j] += __shfl_xor_sync(0xFFFFFFFFu, ed[j], off);
        }
    }
    if (lane == 0) {
#pragma unroll
        for (int j = 0; j < HH; j++) {
            g_es1[warp * HH + j] = es[j];
            g_ed1[warp * HH + j] = ed[j];
        }
    }
}

// layer2: warp per node, single dot over 256 channels
__global__ void k_attn2(const float* __restrict__ a_src, const float* __restrict__ a_dst) {
    int warp = (blockIdx.x * blockDim.x + threadIdx.x) >> 5;
    int lane = threadIdx.x & 31;
    if (warp >= NN) return;
    const float* hrow = g_h2 + (size_t)warp * DD;
    float s1 = 0.f, s2 = 0.f;
#pragma unroll
    for (int j = 0; j < 8; j++) {
        float v = hrow[j * 32 + lane];
        s1 = fmaf(v, a_src[j * 32 + lane], s1);
        s2 = fmaf(v, a_dst[j * 32 + lane], s2);
    }
#pragma unroll
    for (int off = 16; off; off >>= 1) {
        s1 += __shfl_xor_sync(0xFFFFFFFFu, s1, off);
        s2 += __shfl_xor_sync(0xFFFFFFFFu, s2, off);
    }
    if (lane == 0) {
        g_es2[warp] = s1;
        g_ed2[warp] = s2;
    }
}

__device__ __forceinline__ float lrelu(float e) { return e > 0.f ? e : 0.2f * e; }

// ---------------- GAT layer 1: warp per destination node ----------------
// pass1: online softmax (edges striped across lanes, warp merge)
// pass2: aggregate h1[src] * alpha into registers, add bias, ELU -> g_act
__global__ void k_gat1(const float* __restrict__ b1) {
    int n = (blockIdx.x * blockDim.x + threadIdx.x) >> 5;
    int lane = threadIdx.x & 31;
    if (n >= NN) return;
    int beg = g_off[n], end = g_off[n + 1];

    float ed[HH];
#pragma unroll
    for (int j = 0; j < HH; j++) ed[j] = g_ed1[n * HH + j];

    float m[HH], s[HH];
#pragma unroll
    for (int j = 0; j < HH; j++) { m[j] = -1e30f; s[j] = 0.f; }

    for (int i = beg + lane; i < end; i += 32) {
        int sc = g_srcl[i];
#pragma unroll
        for (int j = 0; j < HH; j++) {
            float e = lrelu(g_es1[sc * HH + j] + ed[j]);
            float mn = fmaxf(m[j], e);
            s[j] = s[j] * __expf(m[j] - mn) + __expf(e - mn);
            m[j] = mn;
        }
    }
#pragma unroll
    for (int off = 16; off; off >>= 1) {
#pragma unroll
        for (int j = 0; j < HH; j++) {
            float mo = __shfl_xor_sync(0xFFFFFFFFu, m[j], off);
            float so = __shfl_xor_sync(0xFFFFFFFFu, s[j], off);
            float mn = fmaxf(m[j], mo);
            s[j] = s[j] * __expf(m[j] - mn) + so * __expf(mo - mn);
            m[j] = mn;
        }
    }
    float inv[HH];
#pragma unroll
    for (int j = 0; j < HH; j++) inv[j] = 1.f / (s[j] + 1e-16f);

    float acc[HH];
#pragma unroll
    for (int j = 0; j < HH; j++) acc[j] = 0.f;

    for (int i = beg; i < end; i++) {
        int sc = g_srcl[i];
        const float* hrow = g_h1 + (size_t)sc * DD;
#pragma unroll
        for (int j = 0; j < HH; j++) {
            float e = lrelu(g_es1[sc * HH + j] + ed[j]);
            float w = __expf(e - m[j]) * inv[j];
            acc[j] = fmaf(w, hrow[j * CC + lane], acc[j]);
        }
    }
#pragma unroll
    for (int j = 0; j < HH; j++) {
        float v = acc[j] + b1[j * CC + lane];
        v = v > 0.f ? v : expm1f(v);  // ELU
        g_act[(size_t)n * DD + j * CC + lane] = v;
    }
}

// ---------------- GAT layer 2 (H=1, C=256): warp per destination node ----------------
__global__ void k_gat2(const float* __restrict__ b2, float* __restrict__ out) {
    int n = (blockIdx.x * blockDim.x + threadIdx.x) >> 5;
    int lane = threadIdx.x & 31;
    if (n >= NN) return;
    int beg = g_off[n], end = g_off[n + 1];

    float ed = g_ed2[n];
    float m = -1e30f, s = 0.f;

    for (int i = beg + lane; i < end; i += 32) {
        int sc = g_srcl[i];
        float e = lrelu(g_es2[sc] + ed);
        float mn = fmaxf(m, e);
        s = s * __expf(m - mn) + __expf(e - mn);
        m = mn;
    }
#pragma unroll
    for (int off = 16; off; off >>= 1) {
        float mo = __shfl_xor_sync(0xFFFFFFFFu, m, off);
        float so = __shfl_xor_sync(0xFFFFFFFFu, s, off);
        float mn = fmaxf(m, mo);
        s = s * __expf(m - mn) + so * __expf(mo - mn);
        m = mn;
    }
    float inv = 1.f / (s + 1e-16f);

    float acc[8];
#pragma unroll
    for (int j = 0; j < 8; j++) acc[j] = 0.f;

    for (int i = beg; i < end; i++) {
        int sc = g_srcl[i];
        float e = lrelu(g_es2[sc] + ed);
        float w = __expf(e - m) * inv;
        const float* hrow = g_h2 + (size_t)sc * DD;
#pragma unroll
        for (int j = 0; j < 8; j++)
            acc[j] = fmaf(w, hrow[j * 32 + lane], acc[j]);
    }
#pragma unroll
    for (int j = 0; j < 8; j++)
        out[(size_t)n * DD + j * 32 + lane] = acc[j] + b2[j * 32 + lane];
}

// ---------------- launch ----------------
extern "C" void kernel_launch(void* const* d_in, const int* in_sizes, int n_in,
                              void* d_out, int out_size) {
    const float* x      = (const float*)d_in[0];
    const int*   ei     = (const int*)d_in[1];
    const float* W1     = (const float*)d_in[2];
    const float* a_src1 = (const float*)d_in[3];
    const float* a_dst1 = (const float*)d_in[4];
    const float* b1     = (const float*)d_in[5];
    const float* W2     = (const float*)d_in[6];
    const float* a_src2 = (const float*)d_in[7];
    const float* a_dst2 = (const float*)d_in[8];
    const float* b2     = (const float*)d_in[9];
    float* out = (float*)d_out;

    // CSR build (shared by both layers)
    k_zero_cnt<<<(NN + 255) / 256, 256>>>();
    k_count<<<(ET + 255) / 256, 256>>>(ei);
    k_scan<<<1, 1024>>>();
    k_scatter<<<(ET + 255) / 256, 256>>>(ei);

    dim3 gdim(2, (NN + 127) / 128);
    dim3 bdim(256);

    // layer 1
    k_gemm<1, DIN><<<gdim, bdim>>>(x, W1);
    int warp_grid = (NN * 32 + 255) / 256;
    k_attn1<<<warp_grid, 256>>>(a_src1, a_dst1);
    k_gat1<<<warp_grid, 256>>>(b1);

    // layer 2
    k_gemm<2, DD><<<gdim, bdim>>>(nullptr, W2);
    k_attn2<<<warp_grid, 256>>>(a_src2, a_dst2);
    k_gat2<<<warp_grid, 256>>>(b2, out);
}

// round 3
// speedup vs baseline: 1.1468x; 1.1468x over previous
#include <cuda_runtime.h>
#include <cuda_bf16.h>
#include <math.h>

#define NN 50000
#define NE 500000
#define ET (NE + NN)   /* edges + self loops = 550000 */
#define DIN 128
#define DD 256
#define HH 8
#define CC 32

// ---------------- scratch (static device globals; no allocation) ----------------
__device__ float g_h1[(size_t)NN * DD];   // layer1 GEMM out  [N,256]
__device__ float g_act[(size_t)NN * DD];  // elu(gat1 out)    [N,256]
__device__ float g_h2[(size_t)NN * DD];   // layer2 GEMM out  [N,256]
__device__ float g_es1[NN * HH];
__device__ float g_ed1[NN * HH];
__device__ float g_es2[NN];
__device__ float g_ed2[NN];
__device__ int   g_cnt[NN];
__device__ int   g_off[NN + 1];
__device__ int   g_cur[NN];
__device__ int   g_srcl[ET];
// transposed + bf16-split weights: Bt[n][k] = W[k][n]
__device__ __nv_bfloat16 g_bt1h[256 * 128];
__device__ __nv_bfloat16 g_bt1l[256 * 128];
__device__ __nv_bfloat16 g_bt2h[256 * 256];
__device__ __nv_bfloat16 g_bt2l[256 * 256];

// ---------------- helpers ----------------
__device__ __forceinline__ void cvt2(float a, float b, unsigned& hi, unsigned& lo) {
    __nv_bfloat16 ah = __float2bfloat16_rn(a), bh = __float2bfloat16_rn(b);
    float al = a - __bfloat162float(ah), bl = b - __bfloat162float(bh);
    __nv_bfloat16 alh = __float2bfloat16_rn(al), blh = __float2bfloat16_rn(bl);
    unsigned short au = *(unsigned short*)&ah, bu = *(unsigned short*)&bh;
    unsigned short alu = *(unsigned short*)&alh, blu = *(unsigned short*)&blh;
    hi = (unsigned)au | ((unsigned)bu << 16);
    lo = (unsigned)alu | ((unsigned)blu << 16);
}

__device__ __forceinline__ void mma16816(float* c, const unsigned* a, unsigned b0, unsigned b1) {
    asm volatile(
        "mma.sync.aligned.m16n8k16.row.col.f32.bf16.bf16.f32 "
        "{%0,%1,%2,%3}, {%4,%5,%6,%7}, {%8,%9}, {%0,%1,%2,%3};"
        : "+f"(c[0]), "+f"(c[1]), "+f"(c[2]), "+f"(c[3])
        : "r"(a[0]), "r"(a[1]), "r"(a[2]), "r"(a[3]), "r"(b0), "r"(b1));
}

// ---------------- CSR build ----------------
__global__ void k_zero_cnt() {
    int i = blockIdx.x * blockDim.x + threadIdx.x;
    if (i < NN) g_cnt[i] = 0;
}

__global__ void k_count(const int* __restrict__ ei) {
    int t = blockIdx.x * blockDim.x + threadIdx.x;
    if (t >= ET) return;
    int dst = (t < NE) ? ei[NE + t] : (t - NE);
    atomicAdd(&g_cnt[dst], 1);
}

__global__ void k_scan() {
    __shared__ int part[1024];
    const int CH = (NN + 1023) / 1024;
    int tid = threadIdx.x;
    int start = tid * CH;
    int sum = 0;
    for (int i = 0; i < CH; i++) {
        int idx = start + i;
        if (idx < NN) sum += g_cnt[idx];
    }
    part[tid] = sum;
    __syncthreads();
    for (int d = 1; d < 1024; d <<= 1) {
        int v = (tid >= d) ? part[tid - d] : 0;
        __syncthreads();
        part[tid] += v;
        __syncthreads();
    }
    int run = (tid == 0) ? 0 : part[tid - 1];
    for (int i = 0; i < CH; i++) {
        int idx = start + i;
        if (idx < NN) {
            g_off[idx] = run;
            g_cur[idx] = run;
            run += g_cnt[idx];
        }
    }
    if (tid == 1023) g_off[NN] = run;
}

__global__ void k_scatter(const int* __restrict__ ei) {
    int t = blockIdx.x * blockDim.x + threadIdx.x;
    if (t >= ET) return;
    int src, dst;
    if (t < NE) { src = ei[t]; dst = ei[NE + t]; }
    else        { src = t - NE; dst = t - NE; }
    int pos = atomicAdd(&g_cur[dst], 1);
    g_srcl[pos] = src;
}

// ---------------- weight prep: transpose + bf16 split ----------------
__global__ void k_prepB(const float* __restrict__ W1, const float* __restrict__ W2) {
    int t = blockIdx.x * blockDim.x + threadIdx.x;
    if (t < 256 * 128) {
        int n = t >> 7, k = t & 127;
        float v = W1[k * 256 + n];
        __nv_bfloat16 h = __float2bfloat16_rn(v);
        g_bt1h[n * 128 + k] = h;
        g_bt1l[n * 128 + k] = __float2bfloat16_rn(v - __bfloat162float(h));
    }
    int t2 = t - 256 * 128;
    if (t2 >= 0 && t2 < 256 * 256) {
        int n = t2 >> 8, k = t2 & 255;
        float v = W2[k * 256 + n];
        __nv_bfloat16 h = __float2bfloat16_rn(v);
        g_bt2h[n * 256 + k] = h;
        g_bt2l[n * 256 + k] = __float2bfloat16_rn(v - __bfloat162float(h));
    }
}

// ---------------- HMMA GEMM: C[128-tile, 128-col-tile] via split bf16 ----------------
// smem layout: rows at stride 40 uint16 (80 B) -> conflict-free LDS.32 frag loads.
#define SROW 40

template <int L>
__global__ __launch_bounds__(256)
void k_gemm_mma(const float* __restrict__ Ain) {
    constexpr int KD = (L == 1) ? 128 : 256;
    constexpr int NCH = KD / 32;
    const float* A = (L == 1) ? Ain : g_act;
    float* Cc = (L == 1) ? g_h1 : g_h2;
    const __nv_bfloat16* Bh = (L == 1) ? g_bt1h : g_bt2h;
    const __nv_bfloat16* Bl = (L == 1) ? g_bt1l : g_bt2l;

    __shared__ __align__(16) unsigned short sA[2][128 * SROW];  // [hi/lo][row*40+k]
    __shared__ __align__(16) unsigned short sB[2][128 * SROW];

    int tid = threadIdx.x, wid = tid >> 5, lane = tid & 31;
    int warpM = wid >> 1, warpN = wid & 1;       // 4 x 2 warp grid
    int row0 = blockIdx.y * 128, col0 = blockIdx.x * 128;

    float acc[2][8][4];
#pragma unroll
    for (int mt = 0; mt < 2; mt++)
#pragma unroll
        for (int nt = 0; nt < 8; nt++)
#pragma unroll
            for (int q = 0; q < 4; q++) acc[mt][nt][q] = 0.f;

    for (int ch = 0; ch < NCH; ch++) {
        // ---- stage A: 128 rows x 32 fp32 -> hi/lo bf16 ----
        {
            int r = tid >> 1, half = tid & 1;
            int gr = row0 + r;
            bool v = gr < NN;
            const float* arow = A + (size_t)gr * KD + ch * 32 + half * 16;
            uint4 hi4[2], lo4[2];
#pragma unroll
            for (int g = 0; g < 2; g++) {
                float4 f0 = v ? *(const float4*)(arow + g * 8)     : make_float4(0.f, 0.f, 0.f, 0.f);
                float4 f1 = v ? *(const float4*)(arow + g * 8 + 4) : make_float4(0.f, 0.f, 0.f, 0.f);
                cvt2(f0.x, f0.y, hi4[g].x, lo4[g].x);
                cvt2(f0.z, f0.w, hi4[g].y, lo4[g].y);
                cvt2(f1.x, f1.y, hi4[g].z, lo4[g].z);
                cvt2(f1.z, f1.w, hi4[g].w, lo4[g].w);
            }
            char* dh = (char*)sA[0] + r * 80 + half * 32;
            char* dl = (char*)sA[1] + r * 80 + half * 32;
            *(uint4*)(dh)      = hi4[0];
            *(uint4*)(dh + 16) = hi4[1];
            *(uint4*)(dl)      = lo4[0];
            *(uint4*)(dl + 16) = lo4[1];
        }
        // ---- stage B: 128 n-rows x 32 bf16, hi and lo ----
#pragma unroll
        for (int it = 0; it < 4; it++) {
            int seg = tid * 4 + it;          // 0..1023
            int buf = seg >> 9;              // 0 hi, 1 lo
            int s = seg & 511;
            int n = s >> 2, sg = s & 3;
            const __nv_bfloat16* src = (buf ? Bl : Bh) + (size_t)(col0 + n) * KD + ch * 32 + sg * 8;
            *(uint4*)((char*)sB[buf] + n * 80 + sg * 16) = *(const uint4*)src;
        }
        __syncthreads();

        // ---- 3 passes: hi*hi, hi*lo, lo*hi ----
#pragma unroll
        for (int pass = 0; pass < 3; pass++) {
            const unsigned short* pa = sA[pass == 2 ? 1 : 0];
            const unsigned short* pb = sB[pass == 1 ? 1 : 0];
#pragma unroll
            for (int kt = 0; kt < 2; kt++) {
                int kb = kt * 16 + (lane & 3) * 2;
                unsigned a[2][4];
#pragma unroll
                for (int mt = 0; mt < 2; mt++) {
                    int r = warpM * 32 + mt * 16 + (lane >> 2);
                    a[mt][0] = *(const unsigned*)&pa[r * SROW + kb];
                    a[mt][1] = *(const unsigned*)&pa[(r + 8) * SROW + kb];
                    a[mt][2] = *(const unsigned*)&pa[r * SROW + kb + 8];
                    a[mt][3] = *(const unsigned*)&pa[(r + 8) * SROW + kb + 8];
                }
#pragma unroll
                for (int nt = 0; nt < 8; nt++) {
                    int n = warpN * 64 + nt * 8 + (lane >> 2);
                    unsigned b0 = *(const unsigned*)&pb[n * SROW + kb];
                    unsigned b1 = *(const unsigned*)&pb[n * SROW + kb + 8];
                    mma16816(acc[0][nt], a[0], b0, b1);
                    mma16816(acc[1][nt], a[1], b0, b1);
                }
            }
        }
        __syncthreads();
    }

    // ---- epilogue ----
#pragma unroll
    for (int mt = 0; mt < 2; mt++) {
        int r_lo = row0 + warpM * 32 + mt * 16 + (lane >> 2);
        int cc = col0 + warpN * 64 + (lane & 3) * 2;
#pragma unroll
        for (int nt = 0; nt < 8; nt++) {
            if (r_lo < NN)
                *(float2*)(Cc + (size_t)r_lo * DD + cc + nt * 8) =
                    make_float2(acc[mt][nt][0], acc[mt][nt][1]);
            if (r_lo + 8 < NN)
                *(float2*)(Cc + (size_t)(r_lo + 8) * DD + cc + nt * 8) =
                    make_float2(acc[mt][nt][2], acc[mt][nt][3]);
        }
    }
}

// ---------------- attention coefficients ----------------
__global__ void k_attn1(const float* __restrict__ a_src, const float* __restrict__ a_dst) {
    int warp = (blockIdx.x * blockDim.x + threadIdx.x) >> 5;
    int lane = threadIdx.x & 31;
    if (warp >= NN) return;
    const float* hrow = g_h1 + (size_t)warp * DD;
    float es[HH], ed[HH];
#pragma unroll
    for (int j = 0; j < HH; j++) {
        float v = hrow[j * CC + lane];
        es[j] = v * a_src[j * CC + lane];
        ed[j] = v * a_dst[j * CC + lane];
    }
#pragma unroll
    for (int off = 16; off; off >>= 1) {
#pragma unroll
        for (int j = 0; j < HH; j++) {
            es[j] += __shfl_xor_sync(0xFFFFFFFFu, es[j], off);
            ed[j] += __shfl_xor_sync(0xFFFFFFFFu, ed[j], off);
        }
    }
    if (lane == 0) {
#pragma unroll
        for (int j = 0; j < HH; j++) {
            g_es1[warp * HH + j] = es[j];
            g_ed1[warp * HH + j] = ed[j];
        }
    }
}

__global__ void k_attn2(const float* __restrict__ a_src, const float* __restrict__ a_dst) {
    int warp = (blockIdx.x * blockDim.x + threadIdx.x) >> 5;
    int lane = threadIdx.x & 31;
    if (warp >= NN) return;
    const float* hrow = g_h2 + (size_t)warp * DD;
    float s1 = 0.f, s2 = 0.f;
#pragma unroll
    for (int j = 0; j < 8; j++) {
        float v = hrow[j * 32 + lane];
        s1 = fmaf(v, a_src[j * 32 + lane], s1);
        s2 = fmaf(v, a_dst[j * 32 + lane], s2);
    }
#pragma unroll
    for (int off = 16; off; off >>= 1) {
        s1 += __shfl_xor_sync(0xFFFFFFFFu, s1, off);
        s2 += __shfl_xor_sync(0xFFFFFFFFu, s2, off);
    }
    if (lane == 0) {
        g_es2[warp] = s1;
        g_ed2[warp] = s2;
    }
}

__device__ __forceinline__ float lrelu(float e) { return e > 0.f ? e : 0.2f * e; }

// ---------------- GAT layer 1: warp per destination node ----------------
__global__ void k_gat1(const float* __restrict__ b1) {
    int n = (blockIdx.x * blockDim.x + threadIdx.x) >> 5;
    int lane = threadIdx.x & 31;
    if (n >= NN) return;
    int beg = g_off[n], end = g_off[n + 1];

    float ed[HH];
#pragma unroll
    for (int j = 0; j < HH; j++) ed[j] = g_ed1[n * HH + j];

    float m[HH], s[HH];
#pragma unroll
    for (int j = 0; j < HH; j++) { m[j] = -1e30f; s[j] = 0.f; }

    for (int i = beg + lane; i < end; i += 32) {
        int sc = g_srcl[i];
#pragma unroll
        for (int j = 0; j < HH; j++) {
            float e = lrelu(g_es1[sc * HH + j] + ed[j]);
            float mn = fmaxf(m[j], e);
            s[j] = s[j] * __expf(m[j] - mn) + __expf(e - mn);
            m[j] = mn;
        }
    }
#pragma unroll
    for (int off = 16; off; off >>= 1) {
#pragma unroll
        for (int j = 0; j < HH; j++) {
            float mo = __shfl_xor_sync(0xFFFFFFFFu, m[j], off);
            float so = __shfl_xor_sync(0xFFFFFFFFu, s[j], off);
            float mn = fmaxf(m[j], mo);
            s[j] = s[j] * __expf(m[j] - mn) + so * __expf(mo - mn);
            m[j] = mn;
        }
    }
    float inv[HH];
#pragma unroll
    for (int j = 0; j < HH; j++) inv[j] = 1.f / (s[j] + 1e-16f);

    float acc[HH];
#pragma unroll
    for (int j = 0; j < HH; j++) acc[j] = 0.f;

    for (int i = beg; i < end; i++) {
        int sc = g_srcl[i];
        const float* hrow = g_h1 + (size_t)sc * DD;
#pragma unroll
        for (int j = 0; j < HH; j++) {
            float e = lrelu(g_es1[sc * HH + j] + ed[j]);
            float w = __expf(e - m[j]) * inv[j];
            acc[j] = fmaf(w, hrow[j * CC + lane], acc[j]);
        }
    }
#pragma unroll
    for (int j = 0; j < HH; j++) {
        float v = acc[j] + b1[j * CC + lane];
        v = v > 0.f ? v : expm1f(v);  // ELU
        g_act[(size_t)n * DD + j * CC + lane] = v;
    }
}

// ---------------- GAT layer 2 (H=1, C=256): warp per destination node ----------------
__global__ void k_gat2(const float* __restrict__ b2, float* __restrict__ out) {
    int n = (blockIdx.x * blockDim.x + threadIdx.x) >> 5;
    int lane = threadIdx.x & 31;
    if (n >= NN) return;
    int beg = g_off[n], end = g_off[n + 1];

    float ed = g_ed2[n];
    float m = -1e30f, s = 0.f;

    for (int i = beg + lane; i < end; i += 32) {
        int sc = g_srcl[i];
        float e = lrelu(g_es2[sc] + ed);
        float mn = fmaxf(m, e);
        s = s * __expf(m - mn) + __expf(e - mn);
        m = mn;
    }
#pragma unroll
    for (int off = 16; off; off >>= 1) {
        float mo = __shfl_xor_sync(0xFFFFFFFFu, m, off);
        float so = __shfl_xor_sync(0xFFFFFFFFu, s, off);
        float mn = fmaxf(m, mo);
        s = s * __expf(m - mn) + so * __expf(mo - mn);
        m = mn;
    }
    float inv = 1.f / (s + 1e-16f);

    float acc[8];
#pragma unroll
    for (int j = 0; j < 8; j++) acc[j] = 0.f;

    for (int i = beg; i < end; i++) {
        int sc = g_srcl[i];
        float e = lrelu(g_es2[sc] + ed);
        float w = __expf(e - m) * inv;
        const float* hrow = g_h2 + (size_t)sc * DD;
#pragma unroll
        for (int j = 0; j < 8; j++)
            acc[j] = fmaf(w, hrow[j * 32 + lane], acc[j]);
    }
#pragma unroll
    for (int j = 0; j < 8; j++)
        out[(size_t)n * DD + j * 32 + lane] = acc[j] + b2[j * 32 + lane];
}

// ---------------- launch ----------------
extern "C" void kernel_launch(void* const* d_in, const int* in_sizes, int n_in,
                              void* d_out, int out_size) {
    const float* x      = (const float*)d_in[0];
    const int*   ei     = (const int*)d_in[1];
    const float* W1     = (const float*)d_in[2];
    const float* a_src1 = (const float*)d_in[3];
    const float* a_dst1 = (const float*)d_in[4];
    const float* b1     = (const float*)d_in[5];
    const float* W2     = (const float*)d_in[6];
    const float* a_src2 = (const float*)d_in[7];
    const float* a_dst2 = (const float*)d_in[8];
    const float* b2     = (const float*)d_in[9];
    float* out = (float*)d_out;

    // weight prep + CSR build
    k_prepB<<<(256 * 128 + 256 * 256 + 255) / 256, 256>>>(W1, W2);
    k_zero_cnt<<<(NN + 255) / 256, 256>>>();
    k_count<<<(ET + 255) / 256, 256>>>(ei);
    k_scan<<<1, 1024>>>();
    k_scatter<<<(ET + 255) / 256, 256>>>(ei);

    dim3 gdim(2, (NN + 127) / 128);
    int warp_grid = (NN * 32 + 255) / 256;

    // layer 1
    k_gemm_mma<1><<<gdim, 256>>>(x);
    k_attn1<<<warp_grid, 256>>>(a_src1, a_dst1);
    k_gat1<<<warp_grid, 256>>>(b1);

    // layer 2
    k_gemm_mma<2><<<gdim, 256>>>(nullptr);
    k_attn2<<<warp_grid, 256>>>(a_src2, a_dst2);
    k_gat2<<<warp_grid, 256>>>(b2, out);
}

// round 4
// speedup vs baseline: 1.5036x; 1.3111x over previous
#include <cuda_runtime.h>
#include <cuda_bf16.h>
#include <math.h>

#define NN 50000
#define NE 500000
#define ET (NE + NN)   /* edges + self loops = 550000 */
#define DIN 128
#define DD 256
#define HH 8
#define CC 32

// ---------------- scratch (static device globals; no allocation) ----------------
__device__ float g_h1[(size_t)NN * DD];   // layer1 GEMM out  [N,256]
__device__ float g_act[(size_t)NN * DD];  // elu(gat1 out)    [N,256]
__device__ float g_h2[(size_t)NN * DD];   // layer2 GEMM out  [N,256]
__device__ float g_es1[NN * HH];
__device__ float g_ed1[NN * HH];
__device__ float g_es2[NN];
__device__ float g_ed2[NN];
__device__ int   g_cnt[NN];
__device__ int   g_off[NN + 1];
__device__ int   g_cur[NN];
__device__ int   g_srcl[ET];
#define SCB 512
#define NBL ((NN + SCB - 1) / SCB)   /* 98 */
__device__ int   g_bsum[NBL];
// transposed + bf16-split weights: Bt[n][k] = W[k][n]
__device__ __nv_bfloat16 g_bt1h[256 * 128];
__device__ __nv_bfloat16 g_bt1l[256 * 128];
__device__ __nv_bfloat16 g_bt2h[256 * 256];
__device__ __nv_bfloat16 g_bt2l[256 * 256];

// ---------------- helpers ----------------
__device__ __forceinline__ void cvt2(float a, float b, unsigned& hi, unsigned& lo) {
    __nv_bfloat16 ah = __float2bfloat16_rn(a), bh = __float2bfloat16_rn(b);
    float al = a - __bfloat162float(ah), bl = b - __bfloat162float(bh);
    __nv_bfloat16 alh = __float2bfloat16_rn(al), blh = __float2bfloat16_rn(bl);
    unsigned short au = *(unsigned short*)&ah, bu = *(unsigned short*)&bh;
    unsigned short alu = *(unsigned short*)&alh, blu = *(unsigned short*)&blh;
    hi = (unsigned)au | ((unsigned)bu << 16);
    lo = (unsigned)alu | ((unsigned)blu << 16);
}

__device__ __forceinline__ void mma16816(float* c, const unsigned* a, unsigned b0, unsigned b1) {
    asm volatile(
        "mma.sync.aligned.m16n8k16.row.col.f32.bf16.bf16.f32 "
        "{%0,%1,%2,%3}, {%4,%5,%6,%7}, {%8,%9}, {%0,%1,%2,%3};"
        : "+f"(c[0]), "+f"(c[1]), "+f"(c[2]), "+f"(c[3])
        : "r"(a[0]), "r"(a[1]), "r"(a[2]), "r"(a[3]), "r"(b0), "r"(b1));
}

// ---------------- CSR build ----------------
__global__ void k_zero() {
    int i = blockIdx.x * blockDim.x + threadIdx.x;
    if (i < NN) { g_cnt[i] = 0; g_es2[i] = 0.f; g_ed2[i] = 0.f; }
}

__global__ void k_count(const int* __restrict__ ei) {
    int t = blockIdx.x * blockDim.x + threadIdx.x;
    if (t >= ET) return;
    int dst = (t < NE) ? ei[NE + t] : (t - NE);
    atomicAdd(&g_cnt[dst], 1);
}

// per-block sums of g_cnt
__global__ void k_scan1() {
    __shared__ int wsum[16];
    int t = threadIdx.x;
    int i = blockIdx.x * SCB + t;
    int v = (i < NN) ? g_cnt[i] : 0;
#pragma unroll
    for (int o = 16; o; o >>= 1) v += __shfl_xor_sync(0xFFFFFFFFu, v, o);
    if ((t & 31) == 0) wsum[t >> 5] = v;
    __syncthreads();
    if (t < 16) {
        int s = wsum[t];
#pragma unroll
        for (int o = 8; o; o >>= 1) s += __shfl_xor_sync(0xFFFFu, s, o);
        if (t == 0) g_bsum[blockIdx.x] = s;
    }
}

// exclusive scan of the 98 block sums (single small block)
__global__ void k_scan2() {
    __shared__ int s[128];
    int t = threadIdx.x;
    int v = (t < NBL) ? g_bsum[t] : 0;
    s[t] = v;
    __syncthreads();
#pragma unroll
    for (int d = 1; d < 128; d <<= 1) {
        int u = (t >= d) ? s[t - d] : 0;
        __syncthreads();
        s[t] += u;
        __syncthreads();
    }
    if (t < NBL) g_bsum[t] = s[t] - v;   // exclusive
    if (t == 0) g_off[NN] = ET;
}

// within-block exclusive scan + base
__global__ void k_scan3() {
    __shared__ int s[SCB];
    int t = threadIdx.x;
    int i = blockIdx.x * SCB + t;
    int v = (i < NN) ? g_cnt[i] : 0;
    s[t] = v;
    __syncthreads();
#pragma unroll
    for (int d = 1; d < SCB; d <<= 1) {
        int u = (t >= d) ? s[t - d] : 0;
        __syncthreads();
        s[t] += u;
        __syncthreads();
    }
    if (i < NN) {
        int e = s[t] - v + g_bsum[blockIdx.x];
        g_off[i] = e;
        g_cur[i] = e;
    }
}

__global__ void k_scatter(const int* __restrict__ ei) {
    int t = blockIdx.x * blockDim.x + threadIdx.x;
    if (t >= ET) return;
    int src, dst;
    if (t < NE) { src = ei[t]; dst = ei[NE + t]; }
    else        { src = t - NE; dst = t - NE; }
    int pos = atomicAdd(&g_cur[dst], 1);
    g_srcl[pos] = src;
}

// ---------------- weight prep: transpose + bf16 split ----------------
__global__ void k_prepB(const float* __restrict__ W1, const float* __restrict__ W2) {
    int t = blockIdx.x * blockDim.x + threadIdx.x;
    if (t < 256 * 128) {
        int n = t >> 7, k = t & 127;
        float v = W1[k * 256 + n];
        __nv_bfloat16 h = __float2bfloat16_rn(v);
        g_bt1h[n * 128 + k] = h;
        g_bt1l[n * 128 + k] = __float2bfloat16_rn(v - __bfloat162float(h));
    }
    int t2 = t - 256 * 128;
    if (t2 >= 0 && t2 < 256 * 256) {
        int n = t2 >> 8, k = t2 & 255;
        float v = W2[k * 256 + n];
        __nv_bfloat16 h = __float2bfloat16_rn(v);
        g_bt2h[n * 256 + k] = h;
        g_bt2l[n * 256 + k] = __float2bfloat16_rn(v - __bfloat162float(h));
    }
}

// ---------------- HMMA GEMM + fused attention coefficients ----------------
#define SROW 40

template <int L>
__global__ __launch_bounds__(256)
void k_gemm_mma(const float* __restrict__ Ain,
                const float* __restrict__ asrc, const float* __restrict__ adst) {
    constexpr int KD = (L == 1) ? 128 : 256;
    constexpr int NCH = KD / 32;
    const float* A = (L == 1) ? Ain : g_act;
    float* Cc = (L == 1) ? g_h1 : g_h2;
    const __nv_bfloat16* Bh = (L == 1) ? g_bt1h : g_bt2h;
    const __nv_bfloat16* Bl = (L == 1) ? g_bt1l : g_bt2l;

    __shared__ __align__(16) unsigned short sA[2][128 * SROW];  // [hi/lo][row*40+k]
    __shared__ __align__(16) unsigned short sB[2][128 * SROW];

    int tid = threadIdx.x, wid = tid >> 5, lane = tid & 31;
    int warpM = wid >> 1, warpN = wid & 1;       // 4 x 2 warp grid
    int row0 = blockIdx.y * 128, col0 = blockIdx.x * 128;

    // staging geometry
    int ar = tid >> 1, ahalf = tid & 1;
    int agr = row0 + ar;
    bool av = agr < NN;
    const float* arowb = A + (size_t)agr * KD + ahalf * 16;

    float acc[2][8][4];
#pragma unroll
    for (int mt = 0; mt < 2; mt++)
#pragma unroll
        for (int nt = 0; nt < 8; nt++)
#pragma unroll
            for (int q = 0; q < 4; q++) acc[mt][nt][q] = 0.f;

    float4 pa[4];
    uint4  pb[4];

    // prefetch chunk 0
    {
        const float* p = arowb;
#pragma unroll
        for (int g = 0; g < 4; g++)
            pa[g] = av ? *(const float4*)(p + g * 4) : make_float4(0.f, 0.f, 0.f, 0.f);
#pragma unroll
        for (int it = 0; it < 4; it++) {
            int seg = tid * 4 + it;
            int buf = seg >> 9, s = seg & 511;
            int n = s >> 2, sg = s & 3;
            const __nv_bfloat16* src = (buf ? Bl : Bh) + (size_t)(col0 + n) * KD + sg * 8;
            pb[it] = *(const uint4*)src;
        }
    }

    for (int ch = 0; ch < NCH; ch++) {
        if (ch) __syncthreads();   // prev MMA readers done
        // ---- store staged regs to smem ----
        {
            uint4 hi4[2], lo4[2];
#pragma unroll
            for (int g = 0; g < 2; g++) {
                float4 f0 = pa[g * 2], f1 = pa[g * 2 + 1];
                cvt2(f0.x, f0.y, hi4[g].x, lo4[g].x);
                cvt2(f0.z, f0.w, hi4[g].y, lo4[g].y);
                cvt2(f1.x, f1.y, hi4[g].z, lo4[g].z);
                cvt2(f1.z, f1.w, hi4[g].w, lo4[g].w);
            }
            char* dh = (char*)sA[0] + ar * 80 + ahalf * 32;
            char* dl = (char*)sA[1] + ar * 80 + ahalf * 32;
            *(uint4*)(dh)      = hi4[0];
            *(uint4*)(dh + 16) = hi4[1];
            *(uint4*)(dl)      = lo4[0];
            *(uint4*)(dl + 16) = lo4[1];
#pragma unroll
            for (int it = 0; it < 4; it++) {
                int seg = tid * 4 + it;
                int buf = seg >> 9, s = seg & 511;
                int n = s >> 2, sg = s & 3;
                *(uint4*)((char*)sB[buf] + n * 80 + sg * 16) = pb[it];
            }
        }
        __syncthreads();
        // ---- prefetch next chunk (overlaps with MMA below) ----
        if (ch + 1 < NCH) {
            const float* p = arowb + (ch + 1) * 32;
#pragma unroll
            for (int g = 0; g < 4; g++)
                pa[g] = av ? *(const float4*)(p + g * 4) : make_float4(0.f, 0.f, 0.f, 0.f);
#pragma unroll
            for (int it = 0; it < 4; it++) {
                int seg = tid * 4 + it;
                int buf = seg >> 9, s = seg & 511;
                int n = s >> 2, sg = s & 3;
                const __nv_bfloat16* src = (buf ? Bl : Bh) + (size_t)(col0 + n) * KD + (ch + 1) * 32 + sg * 8;
                pb[it] = *(const uint4*)src;
            }
        }
        // ---- 3 passes: hi*hi, hi*lo, lo*hi ----
#pragma unroll
        for (int pass = 0; pass < 3; pass++) {
            const unsigned short* pA = sA[pass == 2 ? 1 : 0];
            const unsigned short* pB = sB[pass == 1 ? 1 : 0];
#pragma unroll
            for (int kt = 0; kt < 2; kt++) {
                int kb = kt * 16 + (lane & 3) * 2;
                unsigned a[2][4];
#pragma unroll
                for (int mt = 0; mt < 2; mt++) {
                    int r = warpM * 32 + mt * 16 + (lane >> 2);
                    a[mt][0] = *(const unsigned*)&pA[r * SROW + kb];
                    a[mt][1] = *(const unsigned*)&pA[(r + 8) * SROW + kb];
                    a[mt][2] = *(const unsigned*)&pA[r * SROW + kb + 8];
                    a[mt][3] = *(const unsigned*)&pA[(r + 8) * SROW + kb + 8];
                }
#pragma unroll
                for (int nt = 0; nt < 8; nt++) {
                    int n = warpN * 64 + nt * 8 + (lane >> 2);
                    unsigned b0 = *(const unsigned*)&pB[n * SROW + kb];
                    unsigned b1 = *(const unsigned*)&pB[n * SROW + kb + 8];
                    mma16816(acc[0][nt], a[0], b0, b1);
                    mma16816(acc[1][nt], a[1], b0, b1);
                }
            }
        }
    }

    // ---- epilogue: store C ----
#pragma unroll
    for (int mt = 0; mt < 2; mt++) {
        int r_lo = row0 + warpM * 32 + mt * 16 + (lane >> 2);
        int cc = col0 + warpN * 64 + (lane & 3) * 2;
#pragma unroll
        for (int nt = 0; nt < 8; nt++) {
            if (r_lo < NN)
                *(float2*)(Cc + (size_t)r_lo * DD + cc + nt * 8) =
                    make_float2(acc[mt][nt][0], acc[mt][nt][1]);
            if (r_lo + 8 < NN)
                *(float2*)(Cc + (size_t)(r_lo + 8) * DD + cc + nt * 8) =
                    make_float2(acc[mt][nt][2], acc[mt][nt][3]);
        }
    }

    // ---- fused attention coefficient dots ----
    if (L == 1) {
        float pes[2][2][2], ped[2][2][2];
#pragma unroll
        for (int a0 = 0; a0 < 2; a0++)
#pragma unroll
            for (int a1 = 0; a1 < 2; a1++)
#pragma unroll
                for (int a2 = 0; a2 < 2; a2++) { pes[a0][a1][a2] = 0.f; ped[a0][a1][a2] = 0.f; }
#pragma unroll
        for (int nt = 0; nt < 8; nt++) {
            int colg = col0 + warpN * 64 + nt * 8 + (lane & 3) * 2;
            float a0s = __ldg(asrc + colg), a1s = __ldg(asrc + colg + 1);
            float a0d = __ldg(adst + colg), a1d = __ldg(adst + colg + 1);
            int hb = nt >> 2;
#pragma unroll
            for (int mt = 0; mt < 2; mt++) {
                pes[mt][0][hb] += acc[mt][nt][0] * a0s + acc[mt][nt][1] * a1s;
                pes[mt][1][hb] += acc[mt][nt][2] * a0s + acc[mt][nt][3] * a1s;
                ped[mt][0][hb] += acc[mt][nt][0] * a0d + acc[mt][nt][1] * a1d;
                ped[mt][1][hb] += acc[mt][nt][2] * a0d + acc[mt][nt][3] * a1d;
            }
        }
#pragma unroll
        for (int a0 = 0; a0 < 2; a0++)
#pragma unroll
            for (int a1 = 0; a1 < 2; a1++)
#pragma unroll
                for (int a2 = 0; a2 < 2; a2++) {
                    pes[a0][a1][a2] += __shfl_xor_sync(0xFFFFFFFFu, pes[a0][a1][a2], 1);
                    pes[a0][a1][a2] += __shfl_xor_sync(0xFFFFFFFFu, pes[a0][a1][a2], 2);
                    ped[a0][a1][a2] += __shfl_xor_sync(0xFFFFFFFFu, ped[a0][a1][a2], 1);
                    ped[a0][a1][a2] += __shfl_xor_sync(0xFFFFFFFFu, ped[a0][a1][a2], 2);
                }
        if ((lane & 3) == 0) {
#pragma unroll
            for (int mt = 0; mt < 2; mt++)
#pragma unroll
                for (int rs = 0; rs < 2; rs++) {
                    int node = row0 + warpM * 32 + mt * 16 + (lane >> 2) + rs * 8;
                    if (node < NN) {
#pragma unroll
                        for (int hb = 0; hb < 2; hb++) {
                            int head = blockIdx.x * 4 + warpN * 2 + hb;
                            g_es1[node * 8 + head] = pes[mt][rs][hb];
                            g_ed1[node * 8 + head] = ped[mt][rs][hb];
                        }
                    }
                }
        }
    } else {
        float pes[2][2], ped[2][2];
#pragma unroll
        for (int a0 = 0; a0 < 2; a0++)
#pragma unroll
            for (int a1 = 0; a1 < 2; a1++) { pes[a0][a1] = 0.f; ped[a0][a1] = 0.f; }
#pragma unroll
        for (int nt = 0; nt < 8; nt++) {
            int colg = col0 + warpN * 64 + nt * 8 + (lane & 3) * 2;
            float a0s = __ldg(asrc + colg), a1s = __ldg(asrc + colg + 1);
            float a0d = __ldg(adst + colg), a1d = __ldg(adst + colg + 1);
#pragma unroll
            for (int mt = 0; mt < 2; mt++) {
                pes[mt][0] += acc[mt][nt][0] * a0s + acc[mt][nt][1] * a1s;
                pes[mt][1] += acc[mt][nt][2] * a0s + acc[mt][nt][3] * a1s;
                ped[mt][0] += acc[mt][nt][0] * a0d + acc[mt][nt][1] * a1d;
                ped[mt][1] += acc[mt][nt][2] * a0d + acc[mt][nt][3] * a1d;
            }
        }
#pragma unroll
        for (int a0 = 0; a0 < 2; a0++)
#pragma unroll
            for (int a1 = 0; a1 < 2; a1++) {
                pes[a0][a1] += __shfl_xor_sync(0xFFFFFFFFu, pes[a0][a1], 1);
                pes[a0][a1] += __shfl_xor_sync(0xFFFFFFFFu, pes[a0][a1], 2);
                ped[a0][a1] += __shfl_xor_sync(0xFFFFFFFFu, ped[a0][a1], 1);
                ped[a0][a1] += __shfl_xor_sync(0xFFFFFFFFu, ped[a0][a1], 2);
            }
        if ((lane & 3) == 0) {
#pragma unroll
            for (int mt = 0; mt < 2; mt++)
#pragma unroll
                for (int rs = 0; rs < 2; rs++) {
                    int node = row0 + warpM * 32 + mt * 16 + (lane >> 2) + rs * 8;
                    if (node < NN) {
                        atomicAdd(&g_es2[node], pes[mt][rs]);
                        atomicAdd(&g_ed2[node], ped[mt][rs]);
                    }
                }
        }
    }
}

__device__ __forceinline__ float lrelu(float e) { return e > 0.f ? e : 0.2f * e; }

// ---------------- GAT layer 1: warp per destination node ----------------
// passA: max (no MUFU). passB: fused exp/sum/aggregate. normalize at end.
__global__ void k_gat1(const float* __restrict__ b1) {
    int n = (blockIdx.x * blockDim.x + threadIdx.x) >> 5;
    int lane = threadIdx.x & 31;
    if (n >= NN) return;
    int beg = g_off[n], end = g_off[n + 1];

    float ed[HH];
#pragma unroll
    for (int j = 0; j < HH; j++) ed[j] = g_ed1[n * HH + j];

    float m[HH];
#pragma unroll
    for (int j = 0; j < HH; j++) m[j] = -1e30f;

    for (int i = beg + lane; i < end; i += 32) {
        int sc = g_srcl[i];
#pragma unroll
        for (int j = 0; j < HH; j++)
            m[j] = fmaxf(m[j], lrelu(g_es1[sc * HH + j] + ed[j]));
    }
#pragma unroll
    for (int off = 16; off; off >>= 1)
#pragma unroll
        for (int j = 0; j < HH; j++)
            m[j] = fmaxf(m[j], __shfl_xor_sync(0xFFFFFFFFu, m[j], off));

    float s[HH], acc[HH];
#pragma unroll
    for (int j = 0; j < HH; j++) { s[j] = 0.f; acc[j] = 0.f; }

    for (int i = beg; i < end; i++) {
        int sc = g_srcl[i];
        const float* er = g_es1 + sc * HH;
        const float* hrow = g_h1 + (size_t)sc * DD;
#pragma unroll
        for (int j = 0; j < HH; j++) {
            float e = lrelu(er[j] + ed[j]);
            float w = __expf(e - m[j]);
            s[j] += w;
            acc[j] = fmaf(w, hrow[j * CC + lane], acc[j]);
        }
    }
#pragma unroll
    for (int j = 0; j < HH; j++) {
        float v = acc[j] / (s[j] + 1e-16f) + b1[j * CC + lane];
        v = v > 0.f ? v : expm1f(v);  // ELU
        g_act[(size_t)n * DD + j * CC + lane] = v;
    }
}

// ---------------- GAT layer 2 (H=1, C=256): warp per destination node ----------------
__global__ void k_gat2(const float* __restrict__ b2, float* __restrict__ out) {
    int n = (blockIdx.x * blockDim.x + threadIdx.x) >> 5;
    int lane = threadIdx.x & 31;
    if (n >= NN) return;
    int beg = g_off[n], end = g_off[n + 1];

    float ed = g_ed2[n];
    float m = -1e30f;

    for (int i = beg + lane; i < end; i += 32) {
        int sc = g_srcl[i];
        m = fmaxf(m, lrelu(g_es2[sc] + ed));
    }
#pragma unroll
    for (int off = 16; off; off >>= 1)
        m = fmaxf(m, __shfl_xor_sync(0xFFFFFFFFu, m, off));

    float s = 0.f;
    float acc[8];
#pragma unroll
    for (int j = 0; j < 8; j++) acc[j] = 0.f;

    for (int i = beg; i < end; i++) {
        int sc = g_srcl[i];
        float w = __expf(lrelu(g_es2[sc] + ed) - m);
        s += w;
        const float* hrow = g_h2 + (size_t)sc * DD;
#pragma unroll
        for (int j = 0; j < 8; j++)
            acc[j] = fmaf(w, hrow[j * 32 + lane], acc[j]);
    }
    float inv = 1.f / (s + 1e-16f);
#pragma unroll
    for (int j = 0; j < 8; j++)
        out[(size_t)n * DD + j * 32 + lane] = acc[j] * inv + b2[j * 32 + lane];
}

// ---------------- launch ----------------
extern "C" void kernel_launch(void* const* d_in, const int* in_sizes, int n_in,
                              void* d_out, int out_size) {
    const float* x      = (const float*)d_in[0];
    const int*   ei     = (const int*)d_in[1];
    const float* W1     = (const float*)d_in[2];
    const float* a_src1 = (const float*)d_in[3];
    const float* a_dst1 = (const float*)d_in[4];
    const float* b1     = (const float*)d_in[5];
    const float* W2     = (const float*)d_in[6];
    const float* a_src2 = (const float*)d_in[7];
    const float* a_dst2 = (const float*)d_in[8];
    const float* b2     = (const float*)d_in[9];
    float* out = (float*)d_out;

    // weight prep + CSR build
    k_prepB<<<(256 * 128 + 256 * 256 + 255) / 256, 256>>>(W1, W2);
    k_zero<<<(NN + 255) / 256, 256>>>();
    k_count<<<(ET + 255) / 256, 256>>>(ei);
    k_scan1<<<NBL, SCB>>>();
    k_scan2<<<1, 128>>>();
    k_scan3<<<NBL, SCB>>>();
    k_scatter<<<(ET + 255) / 256, 256>>>(ei);

    dim3 gdim(2, (NN + 127) / 128);
    int warp_grid = (NN * 32 + 255) / 256;

    // layer 1
    k_gemm_mma<1><<<gdim, 256>>>(x, a_src1, a_dst1);
    k_gat1<<<warp_grid, 256>>>(b1);

    // layer 2
    k_gemm_mma<2><<<gdim, 256>>>(nullptr, a_src2, a_dst2);
    k_gat2<<<warp_grid, 256>>>(b2, out);
}

// round 5
// speedup vs baseline: 1.7238x; 1.1464x over previous
#include <cuda_runtime.h>
#include <cuda_bf16.h>
#include <math.h>

#define NN 50000
#define NE 500000
#define ET (NE + NN)   /* edges + self loops = 550000 */
#define DIN 128
#define DD 256
#define HH 8
#define CC 32

// ---------------- scratch (static device globals; no allocation) ----------------
__device__ float g_h1[(size_t)NN * DD];   // layer1 GEMM out  [N,256]
__device__ float g_act[(size_t)NN * DD];  // elu(gat1 out)    [N,256]
__device__ float g_h2[(size_t)NN * DD];   // layer2 GEMM out  [N,256]
__device__ float g_es1[NN * HH];
__device__ float g_ed1[NN * HH];
__device__ float g_es2[NN];
__device__ float g_ed2[NN];
__device__ int   g_cnt[NN];
__device__ int   g_off[NN + 1];
__device__ int   g_cur[NN];
__device__ int   g_srcl[ET];
__device__ int   g_dstl[ET];
__device__ float g_w1[(size_t)ET * HH];   // per-edge exp weights, layer1
__device__ float g_w2[ET];                // per-edge exp weights, layer2
#define SCB 512
#define NBL ((NN + SCB - 1) / SCB)   /* 98 */
__device__ int   g_bsum[NBL];
// transposed + bf16-split weights: Bt[n][k] = W[k][n]
__device__ __nv_bfloat16 g_bt1h[256 * 128];
__device__ __nv_bfloat16 g_bt1l[256 * 128];
__device__ __nv_bfloat16 g_bt2h[256 * 256];
__device__ __nv_bfloat16 g_bt2l[256 * 256];

// ---------------- helpers ----------------
__device__ __forceinline__ void cvt2(float a, float b, unsigned& hi, unsigned& lo) {
    __nv_bfloat16 ah = __float2bfloat16_rn(a), bh = __float2bfloat16_rn(b);
    float al = a - __bfloat162float(ah), bl = b - __bfloat162float(bh);
    __nv_bfloat16 alh = __float2bfloat16_rn(al), blh = __float2bfloat16_rn(bl);
    unsigned short au = *(unsigned short*)&ah, bu = *(unsigned short*)&bh;
    unsigned short alu = *(unsigned short*)&alh, blu = *(unsigned short*)&blh;
    hi = (unsigned)au | ((unsigned)bu << 16);
    lo = (unsigned)alu | ((unsigned)blu << 16);
}

__device__ __forceinline__ void mma16816(float* c, const unsigned* a, unsigned b0, unsigned b1) {
    asm volatile(
        "mma.sync.aligned.m16n8k16.row.col.f32.bf16.bf16.f32 "
        "{%0,%1,%2,%3}, {%4,%5,%6,%7}, {%8,%9}, {%0,%1,%2,%3};"
        : "+f"(c[0]), "+f"(c[1]), "+f"(c[2]), "+f"(c[3])
        : "r"(a[0]), "r"(a[1]), "r"(a[2]), "r"(a[3]), "r"(b0), "r"(b1));
}

__device__ __forceinline__ float lrelu(float e) { return e > 0.f ? e : 0.2f * e; }

// ---------------- CSR build ----------------
__global__ void k_zero() {
    int i = blockIdx.x * blockDim.x + threadIdx.x;
    if (i < NN) { g_cnt[i] = 0; g_es2[i] = 0.f; g_ed2[i] = 0.f; }
}

__global__ void k_count(const int* __restrict__ ei) {
    int t = blockIdx.x * blockDim.x + threadIdx.x;
    if (t >= ET) return;
    int dst = (t < NE) ? ei[NE + t] : (t - NE);
    atomicAdd(&g_cnt[dst], 1);
}

__global__ void k_scan1() {
    __shared__ int wsum[16];
    int t = threadIdx.x;
    int i = blockIdx.x * SCB + t;
    int v = (i < NN) ? g_cnt[i] : 0;
#pragma unroll
    for (int o = 16; o; o >>= 1) v += __shfl_xor_sync(0xFFFFFFFFu, v, o);
    if ((t & 31) == 0) wsum[t >> 5] = v;
    __syncthreads();
    if (t < 16) {
        int s = wsum[t];
#pragma unroll
        for (int o = 8; o; o >>= 1) s += __shfl_xor_sync(0xFFFFu, s, o);
        if (t == 0) g_bsum[blockIdx.x] = s;
    }
}

__global__ void k_scan2() {
    __shared__ int s[128];
    int t = threadIdx.x;
    int v = (t < NBL) ? g_bsum[t] : 0;
    s[t] = v;
    __syncthreads();
#pragma unroll
    for (int d = 1; d < 128; d <<= 1) {
        int u = (t >= d) ? s[t - d] : 0;
        __syncthreads();
        s[t] += u;
        __syncthreads();
    }
    if (t < NBL) g_bsum[t] = s[t] - v;   // exclusive
    if (t == 0) g_off[NN] = ET;
}

__global__ void k_scan3() {
    __shared__ int s[SCB];
    int t = threadIdx.x;
    int i = blockIdx.x * SCB + t;
    int v = (i < NN) ? g_cnt[i] : 0;
    s[t] = v;
    __syncthreads();
#pragma unroll
    for (int d = 1; d < SCB; d <<= 1) {
        int u = (t >= d) ? s[t - d] : 0;
        __syncthreads();
        s[t] += u;
        __syncthreads();
    }
    if (i < NN) {
        int e = s[t] - v + g_bsum[blockIdx.x];
        g_off[i] = e;
        g_cur[i] = e;
    }
}

__global__ void k_scatter(const int* __restrict__ ei) {
    int t = blockIdx.x * blockDim.x + threadIdx.x;
    if (t >= ET) return;
    int src, dst;
    if (t < NE) { src = ei[t]; dst = ei[NE + t]; }
    else        { src = t - NE; dst = t - NE; }
    int pos = atomicAdd(&g_cur[dst], 1);
    g_srcl[pos] = src;
    g_dstl[pos] = dst;
}

// ---------------- weight prep: transpose + bf16 split ----------------
__global__ void k_prepB(const float* __restrict__ W1, const float* __restrict__ W2) {
    int t = blockIdx.x * blockDim.x + threadIdx.x;
    if (t < 256 * 128) {
        int n = t >> 7, k = t & 127;
        float v = W1[k * 256 + n];
        __nv_bfloat16 h = __float2bfloat16_rn(v);
        g_bt1h[n * 128 + k] = h;
        g_bt1l[n * 128 + k] = __float2bfloat16_rn(v - __bfloat162float(h));
    }
    int t2 = t - 256 * 128;
    if (t2 >= 0 && t2 < 256 * 256) {
        int n = t2 >> 8, k = t2 & 255;
        float v = W2[k * 256 + n];
        __nv_bfloat16 h = __float2bfloat16_rn(v);
        g_bt2h[n * 256 + k] = h;
        g_bt2l[n * 256 + k] = __float2bfloat16_rn(v - __bfloat162float(h));
    }
}

// ---------------- HMMA GEMM + fused attention coefficients ----------------
#define SROW 40

template <int L>
__global__ __launch_bounds__(256)
void k_gemm_mma(const float* __restrict__ Ain,
                const float* __restrict__ asrc, const float* __restrict__ adst) {
    constexpr int KD = (L == 1) ? 128 : 256;
    constexpr int NCH = KD / 32;
    const float* A = (L == 1) ? Ain : g_act;
    float* Cc = (L == 1) ? g_h1 : g_h2;
    const __nv_bfloat16* Bh = (L == 1) ? g_bt1h : g_bt2h;
    const __nv_bfloat16* Bl = (L == 1) ? g_bt1l : g_bt2l;

    __shared__ __align__(16) unsigned short sA[2][128 * SROW];  // [hi/lo][row*40+k]
    __shared__ __align__(16) unsigned short sB[2][128 * SROW];

    int tid = threadIdx.x, wid = tid >> 5, lane = tid & 31;
    int warpM = wid >> 1, warpN = wid & 1;       // 4 x 2 warp grid
    int row0 = blockIdx.y * 128, col0 = blockIdx.x * 128;

    int ar = tid >> 1, ahalf = tid & 1;
    int agr = row0 + ar;
    bool av = agr < NN;
    const float* arowb = A + (size_t)agr * KD + ahalf * 16;

    float acc[2][8][4];
#pragma unroll
    for (int mt = 0; mt < 2; mt++)
#pragma unroll
        for (int nt = 0; nt < 8; nt++)
#pragma unroll
            for (int q = 0; q < 4; q++) acc[mt][nt][q] = 0.f;

    float4 pa[4];
    uint4  pb[4];

    // prefetch chunk 0
    {
        const float* p = arowb;
#pragma unroll
        for (int g = 0; g < 4; g++)
            pa[g] = av ? *(const float4*)(p + g * 4) : make_float4(0.f, 0.f, 0.f, 0.f);
#pragma unroll
        for (int it = 0; it < 4; it++) {
            int seg = tid * 4 + it;
            int buf = seg >> 9, s = seg & 511;
            int n = s >> 2, sg = s & 3;
            const __nv_bfloat16* src = (buf ? Bl : Bh) + (size_t)(col0 + n) * KD + sg * 8;
            pb[it] = *(const uint4*)src;
        }
    }

    for (int ch = 0; ch < NCH; ch++) {
        if (ch) __syncthreads();   // prev MMA readers done
        // ---- store staged regs to smem ----
        {
            uint4 hi4[2], lo4[2];
#pragma unroll
            for (int g = 0; g < 2; g++) {
                float4 f0 = pa[g * 2], f1 = pa[g * 2 + 1];
                cvt2(f0.x, f0.y, hi4[g].x, lo4[g].x);
                cvt2(f0.z, f0.w, hi4[g].y, lo4[g].y);
                cvt2(f1.x, f1.y, hi4[g].z, lo4[g].z);
                cvt2(f1.z, f1.w, hi4[g].w, lo4[g].w);
            }
            char* dh = (char*)sA[0] + ar * 80 + ahalf * 32;
            char* dl = (char*)sA[1] + ar * 80 + ahalf * 32;
            *(uint4*)(dh)      = hi4[0];
            *(uint4*)(dh + 16) = hi4[1];
            *(uint4*)(dl)      = lo4[0];
            *(uint4*)(dl + 16) = lo4[1];
#pragma unroll
            for (int it = 0; it < 4; it++) {
                int seg = tid * 4 + it;
                int buf = seg >> 9, s = seg & 511;
                int n = s >> 2, sg = s & 3;
                *(uint4*)((char*)sB[buf] + n * 80 + sg * 16) = pb[it];
            }
        }
        __syncthreads();
        // ---- prefetch next chunk (overlaps with MMA below) ----
        if (ch + 1 < NCH) {
            const float* p = arowb + (ch + 1) * 32;
#pragma unroll
            for (int g = 0; g < 4; g++)
                pa[g] = av ? *(const float4*)(p + g * 4) : make_float4(0.f, 0.f, 0.f, 0.f);
#pragma unroll
            for (int it = 0; it < 4; it++) {
                int seg = tid * 4 + it;
                int buf = seg >> 9, s = seg & 511;
                int n = s >> 2, sg = s & 3;
                const __nv_bfloat16* src = (buf ? Bl : Bh) + (size_t)(col0 + n) * KD + (ch + 1) * 32 + sg * 8;
                pb[it] = *(const uint4*)src;
            }
        }
        // ---- fragment-reuse MMA: load aHi/aLo/bHi/bLo once, 3 products ----
#pragma unroll
        for (int kt = 0; kt < 2; kt++) {
            int kb = kt * 16 + (lane & 3) * 2;
            unsigned aH[2][4], aL[2][4];
#pragma unroll
            for (int mt = 0; mt < 2; mt++) {
                int r = warpM * 32 + mt * 16 + (lane >> 2);
                aH[mt][0] = *(const unsigned*)&sA[0][r * SROW + kb];
                aH[mt][1] = *(const unsigned*)&sA[0][(r + 8) * SROW + kb];
                aH[mt][2] = *(const unsigned*)&sA[0][r * SROW + kb + 8];
                aH[mt][3] = *(const unsigned*)&sA[0][(r + 8) * SROW + kb + 8];
                aL[mt][0] = *(const unsigned*)&sA[1][r * SROW + kb];
                aL[mt][1] = *(const unsigned*)&sA[1][(r + 8) * SROW + kb];
                aL[mt][2] = *(const unsigned*)&sA[1][r * SROW + kb + 8];
                aL[mt][3] = *(const unsigned*)&sA[1][(r + 8) * SROW + kb + 8];
            }
#pragma unroll
            for (int nt = 0; nt < 8; nt++) {
                int n = warpN * 64 + nt * 8 + (lane >> 2);
                unsigned bH0 = *(const unsigned*)&sB[0][n * SROW + kb];
                unsigned bH1 = *(const unsigned*)&sB[0][n * SROW + kb + 8];
                unsigned bL0 = *(const unsigned*)&sB[1][n * SROW + kb];
                unsigned bL1 = *(const unsigned*)&sB[1][n * SROW + kb + 8];
                mma16816(acc[0][nt], aH[0], bH0, bH1);
                mma16816(acc[1][nt], aH[1], bH0, bH1);
                mma16816(acc[0][nt], aH[0], bL0, bL1);
                mma16816(acc[1][nt], aH[1], bL0, bL1);
                mma16816(acc[0][nt], aL[0], bH0, bH1);
                mma16816(acc[1][nt], aL[1], bH0, bH1);
            }
        }
    }

    // ---- epilogue: store C ----
#pragma unroll
    for (int mt = 0; mt < 2; mt++) {
        int r_lo = row0 + warpM * 32 + mt * 16 + (lane >> 2);
        int cc = col0 + warpN * 64 + (lane & 3) * 2;
#pragma unroll
        for (int nt = 0; nt < 8; nt++) {
            if (r_lo < NN)
                *(float2*)(Cc + (size_t)r_lo * DD + cc + nt * 8) =
                    make_float2(acc[mt][nt][0], acc[mt][nt][1]);
            if (r_lo + 8 < NN)
                *(float2*)(Cc + (size_t)(r_lo + 8) * DD + cc + nt * 8) =
                    make_float2(acc[mt][nt][2], acc[mt][nt][3]);
        }
    }

    // ---- fused attention coefficient dots ----
    if (L == 1) {
        float pes[2][2][2], ped[2][2][2];
#pragma unroll
        for (int a0 = 0; a0 < 2; a0++)
#pragma unroll
            for (int a1 = 0; a1 < 2; a1++)
#pragma unroll
                for (int a2 = 0; a2 < 2; a2++) { pes[a0][a1][a2] = 0.f; ped[a0][a1][a2] = 0.f; }
#pragma unroll
        for (int nt = 0; nt < 8; nt++) {
            int colg = col0 + warpN * 64 + nt * 8 + (lane & 3) * 2;
            float a0s = __ldg(asrc + colg), a1s = __ldg(asrc + colg + 1);
            float a0d = __ldg(adst + colg), a1d = __ldg(adst + colg + 1);
            int hb = nt >> 2;
#pragma unroll
            for (int mt = 0; mt < 2; mt++) {
                pes[mt][0][hb] += acc[mt][nt][0] * a0s + acc[mt][nt][1] * a1s;
                pes[mt][1][hb] += acc[mt][nt][2] * a0s + acc[mt][nt][3] * a1s;
                ped[mt][0][hb] += acc[mt][nt][0] * a0d + acc[mt][nt][1] * a1d;
                ped[mt][1][hb] += acc[mt][nt][2] * a0d + acc[mt][nt][3] * a1d;
            }
        }
#pragma unroll
        for (int a0 = 0; a0 < 2; a0++)
#pragma unroll
            for (int a1 = 0; a1 < 2; a1++)
#pragma unroll
                for (int a2 = 0; a2 < 2; a2++) {
                    pes[a0][a1][a2] += __shfl_xor_sync(0xFFFFFFFFu, pes[a0][a1][a2], 1);
                    pes[a0][a1][a2] += __shfl_xor_sync(0xFFFFFFFFu, pes[a0][a1][a2], 2);
                    ped[a0][a1][a2] += __shfl_xor_sync(0xFFFFFFFFu, ped[a0][a1][a2], 1);
                    ped[a0][a1][a2] += __shfl_xor_sync(0xFFFFFFFFu, ped[a0][a1][a2], 2);
                }
        if ((lane & 3) == 0) {
#pragma unroll
            for (int mt = 0; mt < 2; mt++)
#pragma unroll
                for (int rs = 0; rs < 2; rs++) {
                    int node = row0 + warpM * 32 + mt * 16 + (lane >> 2) + rs * 8;
                    if (node < NN) {
#pragma unroll
                        for (int hb = 0; hb < 2; hb++) {
                            int head = blockIdx.x * 4 + warpN * 2 + hb;
                            g_es1[node * 8 + head] = pes[mt][rs][hb];
                            g_ed1[node * 8 + head] = ped[mt][rs][hb];
                        }
                    }
                }
        }
    } else {
        float pes[2][2], ped[2][2];
#pragma unroll
        for (int a0 = 0; a0 < 2; a0++)
#pragma unroll
            for (int a1 = 0; a1 < 2; a1++) { pes[a0][a1] = 0.f; ped[a0][a1] = 0.f; }
#pragma unroll
        for (int nt = 0; nt < 8; nt++) {
            int colg = col0 + warpN * 64 + nt * 8 + (lane & 3) * 2;
            float a0s = __ldg(asrc + colg), a1s = __ldg(asrc + colg + 1);
            float a0d = __ldg(adst + colg), a1d = __ldg(adst + colg + 1);
#pragma unroll
            for (int mt = 0; mt < 2; mt++) {
                pes[mt][0] += acc[mt][nt][0] * a0s + acc[mt][nt][1] * a1s;
                pes[mt][1] += acc[mt][nt][2] * a0s + acc[mt][nt][3] * a1s;
                ped[mt][0] += acc[mt][nt][0] * a0d + acc[mt][nt][1] * a1d;
                ped[mt][1] += acc[mt][nt][2] * a0d + acc[mt][nt][3] * a1d;
            }
        }
#pragma unroll
        for (int a0 = 0; a0 < 2; a0++)
#pragma unroll
            for (int a1 = 0; a1 < 2; a1++) {
                pes[a0][a1] += __shfl_xor_sync(0xFFFFFFFFu, pes[a0][a1], 1);
                pes[a0][a1] += __shfl_xor_sync(0xFFFFFFFFu, pes[a0][a1], 2);
                ped[a0][a1] += __shfl_xor_sync(0xFFFFFFFFu, ped[a0][a1], 1);
                ped[a0][a1] += __shfl_xor_sync(0xFFFFFFFFu, ped[a0][a1], 2);
            }
        if ((lane & 3) == 0) {
#pragma unroll
            for (int mt = 0; mt < 2; mt++)
#pragma unroll
                for (int rs = 0; rs < 2; rs++) {
                    int node = row0 + warpM * 32 + mt * 16 + (lane >> 2) + rs * 8;
                    if (node < NN) {
                        atomicAdd(&g_es2[node], pes[mt][rs]);
                        atomicAdd(&g_ed2[node], ped[mt][rs]);
                    }
                }
        }
    }
}

// ---------------- per-edge exp weights (no max subtraction: e in safe range) ----------------
__global__ void k_w1() {
    int i = blockIdx.x * blockDim.x + threadIdx.x;
    if (i >= ET) return;
    int sc = g_srcl[i], dn = g_dstl[i];
    float4 e0 = *(const float4*)(g_es1 + sc * 8);
    float4 e1 = *(const float4*)(g_es1 + sc * 8 + 4);
    float4 d0 = *(const float4*)(g_ed1 + dn * 8);
    float4 d1 = *(const float4*)(g_ed1 + dn * 8 + 4);
    float4 w0, w1;
    w0.x = __expf(lrelu(e0.x + d0.x));
    w0.y = __expf(lrelu(e0.y + d0.y));
    w0.z = __expf(lrelu(e0.z + d0.z));
    w0.w = __expf(lrelu(e0.w + d0.w));
    w1.x = __expf(lrelu(e1.x + d1.x));
    w1.y = __expf(lrelu(e1.y + d1.y));
    w1.z = __expf(lrelu(e1.z + d1.z));
    w1.w = __expf(lrelu(e1.w + d1.w));
    *(float4*)(g_w1 + (size_t)i * 8)     = w0;
    *(float4*)(g_w1 + (size_t)i * 8 + 4) = w1;
}

__global__ void k_w2() {
    int i = blockIdx.x * blockDim.x + threadIdx.x;
    if (i >= ET) return;
    g_w2[i] = __expf(lrelu(g_es2[g_srcl[i]] + g_ed2[g_dstl[i]]));
}

// ---------------- GAT layer 1: warp per destination node, single fused pass ----------------
__global__ void k_gat1(const float* __restrict__ b1) {
    int n = (blockIdx.x * blockDim.x + threadIdx.x) >> 5;
    int lane = threadIdx.x & 31;
    if (n >= NN) return;
    int beg = g_off[n], end = g_off[n + 1];

    float s[HH], acc[HH];
#pragma unroll
    for (int j = 0; j < HH; j++) { s[j] = 0.f; acc[j] = 0.f; }

    for (int i = beg; i < end; i++) {
        int sc = g_srcl[i];
        const float* hrow = g_h1 + (size_t)sc * DD;
        const float* wr = g_w1 + (size_t)i * 8;
#pragma unroll
        for (int j = 0; j < HH; j++) {
            float w = wr[j];
            s[j] += w;
            acc[j] = fmaf(w, hrow[j * CC + lane], acc[j]);
        }
    }
#pragma unroll
    for (int j = 0; j < HH; j++) {
        float v = acc[j] / (s[j] + 1e-16f) + b1[j * CC + lane];
        v = v > 0.f ? v : expm1f(v);  // ELU
        g_act[(size_t)n * DD + j * CC + lane] = v;
    }
}

// ---------------- GAT layer 2 (H=1, C=256): warp per destination node ----------------
__global__ void k_gat2(const float* __restrict__ b2, float* __restrict__ out) {
    int n = (blockIdx.x * blockDim.x + threadIdx.x) >> 5;
    int lane = threadIdx.x & 31;
    if (n >= NN) return;
    int beg = g_off[n], end = g_off[n + 1];

    float s = 0.f;
    float acc[8];
#pragma unroll
    for (int j = 0; j < 8; j++) acc[j] = 0.f;

    for (int i = beg; i < end; i++) {
        int sc = g_srcl[i];
        float w = g_w2[i];
        s += w;
        const float* hrow = g_h2 + (size_t)sc * DD;
#pragma unroll
        for (int j = 0; j < 8; j++)
            acc[j] = fmaf(w, hrow[j * 32 + lane], acc[j]);
    }
    float inv = 1.f / (s + 1e-16f);
#pragma unroll
    for (int j = 0; j < 8; j++)
        out[(size_t)n * DD + j * 32 + lane] = acc[j] * inv + b2[j * 32 + lane];
}

// ---------------- launch ----------------
extern "C" void kernel_launch(void* const* d_in, const int* in_sizes, int n_in,
                              void* d_out, int out_size) {
    const float* x      = (const float*)d_in[0];
    const int*   ei     = (const int*)d_in[1];
    const float* W1     = (const float*)d_in[2];
    const float* a_src1 = (const float*)d_in[3];
    const float* a_dst1 = (const float*)d_in[4];
    const float* b1     = (const float*)d_in[5];
    const float* W2     = (const float*)d_in[6];
    const float* a_src2 = (const float*)d_in[7];
    const float* a_dst2 = (const float*)d_in[8];
    const float* b2     = (const float*)d_in[9];
    float* out = (float*)d_out;

    // weight prep + CSR build
    k_prepB<<<(256 * 128 + 256 * 256 + 255) / 256, 256>>>(W1, W2);
    k_zero<<<(NN + 255) / 256, 256>>>();
    k_count<<<(ET + 255) / 256, 256>>>(ei);
    k_scan1<<<NBL, SCB>>>();
    k_scan2<<<1, 128>>>();
    k_scan3<<<NBL, SCB>>>();
    k_scatter<<<(ET + 255) / 256, 256>>>(ei);

    dim3 gdim(2, (NN + 127) / 128);
    int warp_grid = (NN * 32 + 255) / 256;
    int edge_grid = (ET + 255) / 256;

    // layer 1
    k_gemm_mma<1><<<gdim, 256>>>(x, a_src1, a_dst1);
    k_w1<<<edge_grid, 256>>>();
    k_gat1<<<warp_grid, 256>>>(b1);

    // layer 2
    k_gemm_mma<2><<<gdim, 256>>>(nullptr, a_src2, a_dst2);
    k_w2<<<edge_grid, 256>>>();
    k_gat2<<<warp_grid, 256>>>(b2, out);
}

// round 6
// speedup vs baseline: 1.8214x; 1.0566x over previous
#include <cuda_runtime.h>
#include <cuda_bf16.h>
#include <math.h>

#define NN 50000
#define NE 500000
#define ET (NE + NN)   /* edges + self loops = 550000 */
#define DIN 128
#define DD 256
#define HH 8
#define CC 32

// ---------------- scratch (static device globals; no allocation) ----------------
__device__ float g_h1[(size_t)NN * DD];   // layer1 GEMM out  [N,256]
__device__ float g_act[(size_t)NN * DD];  // elu(gat1 out)    [N,256]
__device__ float g_h2[(size_t)NN * DD];   // layer2 GEMM out  [N,256]
__device__ float g_es1[NN * HH];
__device__ float g_ed1[NN * HH];
__device__ float g_es2[NN];
__device__ float g_ed2[NN];
__device__ int   g_cnt[NN];
__device__ int   g_off[NN + 1];
__device__ int   g_cur[NN];
__device__ int   g_srcl[ET];
__device__ int   g_dstl[ET];
__device__ float g_w1[(size_t)ET * HH];   // per-edge exp weights, layer1
__device__ float g_w2[ET];                // per-edge exp weights, layer2
#define SCB 512
#define NBL ((NN + SCB - 1) / SCB)   /* 98 */
__device__ int   g_bsum[NBL];
// transposed + bf16-split weights: Bt[n][k] = W[k][n]
__device__ __nv_bfloat16 g_bt1h[256 * 128];
__device__ __nv_bfloat16 g_bt1l[256 * 128];
__device__ __nv_bfloat16 g_bt2h[256 * 256];
__device__ __nv_bfloat16 g_bt2l[256 * 256];

// ---------------- helpers ----------------
__device__ __forceinline__ void cvt2(float a, float b, unsigned& hi, unsigned& lo) {
    __nv_bfloat16 ah = __float2bfloat16_rn(a), bh = __float2bfloat16_rn(b);
    float al = a - __bfloat162float(ah), bl = b - __bfloat162float(bh);
    __nv_bfloat16 alh = __float2bfloat16_rn(al), blh = __float2bfloat16_rn(bl);
    unsigned short au = *(unsigned short*)&ah, bu = *(unsigned short*)&bh;
    unsigned short alu = *(unsigned short*)&alh, blu = *(unsigned short*)&blh;
    hi = (unsigned)au | ((unsigned)bu << 16);
    lo = (unsigned)alu | ((unsigned)blu << 16);
}

__device__ __forceinline__ void mma16816(float* c, const unsigned* a, unsigned b0, unsigned b1) {
    asm volatile(
        "mma.sync.aligned.m16n8k16.row.col.f32.bf16.bf16.f32 "
        "{%0,%1,%2,%3}, {%4,%5,%6,%7}, {%8,%9}, {%0,%1,%2,%3};"
        : "+f"(c[0]), "+f"(c[1]), "+f"(c[2]), "+f"(c[3])
        : "r"(a[0]), "r"(a[1]), "r"(a[2]), "r"(a[3]), "r"(b0), "r"(b1));
}

__device__ __forceinline__ float lrelu(float e) { return e > 0.f ? e : 0.2f * e; }

// ---------------- CSR build ----------------
__global__ void k_zero() {
    int i = blockIdx.x * blockDim.x + threadIdx.x;
    if (i < NN) { g_cnt[i] = 0; g_es2[i] = 0.f; g_ed2[i] = 0.f; }
}

__global__ void k_count(const int* __restrict__ ei) {
    int t = blockIdx.x * blockDim.x + threadIdx.x;
    if (t >= ET) return;
    int dst = (t < NE) ? ei[NE + t] : (t - NE);
    atomicAdd(&g_cnt[dst], 1);
}

__global__ void k_scan1() {
    __shared__ int wsum[16];
    int t = threadIdx.x;
    int i = blockIdx.x * SCB + t;
    int v = (i < NN) ? g_cnt[i] : 0;
#pragma unroll
    for (int o = 16; o; o >>= 1) v += __shfl_xor_sync(0xFFFFFFFFu, v, o);
    if ((t & 31) == 0) wsum[t >> 5] = v;
    __syncthreads();
    if (t < 16) {
        int s = wsum[t];
#pragma unroll
        for (int o = 8; o; o >>= 1) s += __shfl_xor_sync(0xFFFFu, s, o);
        if (t == 0) g_bsum[blockIdx.x] = s;
    }
}

__global__ void k_scan2() {
    __shared__ int s[128];
    int t = threadIdx.x;
    int v = (t < NBL) ? g_bsum[t] : 0;
    s[t] = v;
    __syncthreads();
#pragma unroll
    for (int d = 1; d < 128; d <<= 1) {
        int u = (t >= d) ? s[t - d] : 0;
        __syncthreads();
        s[t] += u;
        __syncthreads();
    }
    if (t < NBL) g_bsum[t] = s[t] - v;   // exclusive
    if (t == 0) g_off[NN] = ET;
}

__global__ void k_scan3() {
    __shared__ int s[SCB];
    int t = threadIdx.x;
    int i = blockIdx.x * SCB + t;
    int v = (i < NN) ? g_cnt[i] : 0;
    s[t] = v;
    __syncthreads();
#pragma unroll
    for (int d = 1; d < SCB; d <<= 1) {
        int u = (t >= d) ? s[t - d] : 0;
        __syncthreads();
        s[t] += u;
        __syncthreads();
    }
    if (i < NN) {
        int e = s[t] - v + g_bsum[blockIdx.x];
        g_off[i] = e;
        g_cur[i] = e;
    }
}

__global__ void k_scatter(const int* __restrict__ ei) {
    int t = blockIdx.x * blockDim.x + threadIdx.x;
    if (t >= ET) return;
    int src, dst;
    if (t < NE) { src = ei[t]; dst = ei[NE + t]; }
    else        { src = t - NE; dst = t - NE; }
    int pos = atomicAdd(&g_cur[dst], 1);
    g_srcl[pos] = src;
    g_dstl[pos] = dst;
}

// ---------------- weight prep: transpose + bf16 split ----------------
__global__ void k_prepB(const float* __restrict__ W1, const float* __restrict__ W2) {
    int t = blockIdx.x * blockDim.x + threadIdx.x;
    if (t < 256 * 128) {
        int n = t >> 7, k = t & 127;
        float v = W1[k * 256 + n];
        __nv_bfloat16 h = __float2bfloat16_rn(v);
        g_bt1h[n * 128 + k] = h;
        g_bt1l[n * 128 + k] = __float2bfloat16_rn(v - __bfloat162float(h));
    }
    int t2 = t - 256 * 128;
    if (t2 >= 0 && t2 < 256 * 256) {
        int n = t2 >> 8, k = t2 & 255;
        float v = W2[k * 256 + n];
        __nv_bfloat16 h = __float2bfloat16_rn(v);
        g_bt2h[n * 256 + k] = h;
        g_bt2l[n * 256 + k] = __float2bfloat16_rn(v - __bfloat162float(h));
    }
}

// ---------------- HMMA GEMM, double-buffered, + fused attention coefficients ----------------
#define SROW 40
// dynamic smem layout (bytes): buffer b at b*40960
//   A hi: +0, A lo: +10240, B hi: +20480, B lo: +30720; total 81920
#define BUFSZ 40960
#define PLANE 10240

template <int L>
__global__ __launch_bounds__(256)
void k_gemm_mma(const float* __restrict__ Ain,
                const float* __restrict__ asrc, const float* __restrict__ adst) {
    constexpr int KD = (L == 1) ? 128 : 256;
    constexpr int NCH = KD / 32;
    const float* A = (L == 1) ? Ain : g_act;
    float* Cc = (L == 1) ? g_h1 : g_h2;
    const __nv_bfloat16* Bh = (L == 1) ? g_bt1h : g_bt2h;
    const __nv_bfloat16* Bl = (L == 1) ? g_bt1l : g_bt2l;

    extern __shared__ char smem[];

    int tid = threadIdx.x, wid = tid >> 5, lane = tid & 31;
    int warpM = wid >> 1, warpN = wid & 1;       // 4 x 2 warp grid
    int row0 = blockIdx.y * 128, col0 = blockIdx.x * 128;

    int ar = tid >> 1, ahalf = tid & 1;
    int agr = row0 + ar;
    bool av = agr < NN;
    const float* arowb = A + (size_t)agr * KD + ahalf * 16;

    float acc[2][8][4];
#pragma unroll
    for (int mt = 0; mt < 2; mt++)
#pragma unroll
        for (int nt = 0; nt < 8; nt++)
#pragma unroll
            for (int q = 0; q < 4; q++) acc[mt][nt][q] = 0.f;

    float4 pa[4];
    uint4  pb[4];

    // ---- load + stage chunk 0 into buffer 0 ----
    {
        const float* p = arowb;
#pragma unroll
        for (int g = 0; g < 4; g++)
            pa[g] = av ? *(const float4*)(p + g * 4) : make_float4(0.f, 0.f, 0.f, 0.f);
#pragma unroll
        for (int it = 0; it < 4; it++) {
            int seg = tid * 4 + it;
            int buf = seg >> 9, s = seg & 511;
            int n = s >> 2, sg = s & 3;
            const __nv_bfloat16* src = (buf ? Bl : Bh) + (size_t)(col0 + n) * KD + sg * 8;
            pb[it] = *(const uint4*)src;
        }
        uint4 hi4[2], lo4[2];
#pragma unroll
        for (int g = 0; g < 2; g++) {
            float4 f0 = pa[g * 2], f1 = pa[g * 2 + 1];
            cvt2(f0.x, f0.y, hi4[g].x, lo4[g].x);
            cvt2(f0.z, f0.w, hi4[g].y, lo4[g].y);
            cvt2(f1.x, f1.y, hi4[g].z, lo4[g].z);
            cvt2(f1.z, f1.w, hi4[g].w, lo4[g].w);
        }
        char* dh = smem + ar * 80 + ahalf * 32;
        *(uint4*)(dh)              = hi4[0];
        *(uint4*)(dh + 16)         = hi4[1];
        *(uint4*)(dh + PLANE)      = lo4[0];
        *(uint4*)(dh + PLANE + 16) = lo4[1];
#pragma unroll
        for (int it = 0; it < 4; it++) {
            int seg = tid * 4 + it;
            int buf = seg >> 9, s = seg & 511;
            int n = s >> 2, sg = s & 3;
            *(uint4*)(smem + 20480 + buf * PLANE + n * 80 + sg * 16) = pb[it];
        }
    }
    __syncthreads();

    for (int ch = 0; ch < NCH; ch++) {
        // ---- prefetch next chunk's globals (latency covered by MMA below) ----
        if (ch + 1 < NCH) {
            const float* p = arowb + (ch + 1) * 32;
#pragma unroll
            for (int g = 0; g < 4; g++)
                pa[g] = av ? *(const float4*)(p + g * 4) : make_float4(0.f, 0.f, 0.f, 0.f);
#pragma unroll
            for (int it = 0; it < 4; it++) {
                int seg = tid * 4 + it;
                int buf = seg >> 9, s = seg & 511;
                int n = s >> 2, sg = s & 3;
                const __nv_bfloat16* src = (buf ? Bl : Bh) + (size_t)(col0 + n) * KD + (ch + 1) * 32 + sg * 8;
                pb[it] = *(const uint4*)src;
            }
        }
        // ---- MMA on current buffer: fragment reuse, 3 split products ----
        {
            const char* base = smem + (ch & 1) * BUFSZ;
            const unsigned short* aHp = (const unsigned short*)(base);
            const unsigned short* aLp = (const unsigned short*)(base + PLANE);
            const unsigned short* bHp = (const unsigned short*)(base + 20480);
            const unsigned short* bLp = (const unsigned short*)(base + 30720);
#pragma unroll
            for (int kt = 0; kt < 2; kt++) {
                int kb = kt * 16 + (lane & 3) * 2;
                unsigned aH[2][4], aL[2][4];
#pragma unroll
                for (int mt = 0; mt < 2; mt++) {
                    int r = warpM * 32 + mt * 16 + (lane >> 2);
                    aH[mt][0] = *(const unsigned*)&aHp[r * SROW + kb];
                    aH[mt][1] = *(const unsigned*)&aHp[(r + 8) * SROW + kb];
                    aH[mt][2] = *(const unsigned*)&aHp[r * SROW + kb + 8];
                    aH[mt][3] = *(const unsigned*)&aHp[(r + 8) * SROW + kb + 8];
                    aL[mt][0] = *(const unsigned*)&aLp[r * SROW + kb];
                    aL[mt][1] = *(const unsigned*)&aLp[(r + 8) * SROW + kb];
                    aL[mt][2] = *(const unsigned*)&aLp[r * SROW + kb + 8];
                    aL[mt][3] = *(const unsigned*)&aLp[(r + 8) * SROW + kb + 8];
                }
#pragma unroll
                for (int nt = 0; nt < 8; nt++) {
                    int n = warpN * 64 + nt * 8 + (lane >> 2);
                    unsigned bH0 = *(const unsigned*)&bHp[n * SROW + kb];
                    unsigned bH1 = *(const unsigned*)&bHp[n * SROW + kb + 8];
                    unsigned bL0 = *(const unsigned*)&bLp[n * SROW + kb];
                    unsigned bL1 = *(const unsigned*)&bLp[n * SROW + kb + 8];
                    mma16816(acc[0][nt], aH[0], bH0, bH1);
                    mma16816(acc[1][nt], aH[1], bH0, bH1);
                    mma16816(acc[0][nt], aH[0], bL0, bL1);
                    mma16816(acc[1][nt], aH[1], bL0, bL1);
                    mma16816(acc[0][nt], aL[0], bH0, bH1);
                    mma16816(acc[1][nt], aL[1], bH0, bH1);
                }
            }
        }
        // ---- stage next chunk into the other buffer ----
        if (ch + 1 < NCH) {
            char* base = smem + ((ch + 1) & 1) * BUFSZ;
            uint4 hi4[2], lo4[2];
#pragma unroll
            for (int g = 0; g < 2; g++) {
                float4 f0 = pa[g * 2], f1 = pa[g * 2 + 1];
                cvt2(f0.x, f0.y, hi4[g].x, lo4[g].x);
                cvt2(f0.z, f0.w, hi4[g].y, lo4[g].y);
                cvt2(f1.x, f1.y, hi4[g].z, lo4[g].z);
                cvt2(f1.z, f1.w, hi4[g].w, lo4[g].w);
            }
            char* dh = base + ar * 80 + ahalf * 32;
            *(uint4*)(dh)              = hi4[0];
            *(uint4*)(dh + 16)         = hi4[1];
            *(uint4*)(dh + PLANE)      = lo4[0];
            *(uint4*)(dh + PLANE + 16) = lo4[1];
#pragma unroll
            for (int it = 0; it < 4; it++) {
                int seg = tid * 4 + it;
                int buf = seg >> 9, s = seg & 511;
                int n = s >> 2, sg = s & 3;
                *(uint4*)(base + 20480 + buf * PLANE + n * 80 + sg * 16) = pb[it];
            }
        }
        __syncthreads();
    }

    // ---- epilogue: store C ----
#pragma unroll
    for (int mt = 0; mt < 2; mt++) {
        int r_lo = row0 + warpM * 32 + mt * 16 + (lane >> 2);
        int cc = col0 + warpN * 64 + (lane & 3) * 2;
#pragma unroll
        for (int nt = 0; nt < 8; nt++) {
            if (r_lo < NN)
                *(float2*)(Cc + (size_t)r_lo * DD + cc + nt * 8) =
                    make_float2(acc[mt][nt][0], acc[mt][nt][1]);
            if (r_lo + 8 < NN)
                *(float2*)(Cc + (size_t)(r_lo + 8) * DD + cc + nt * 8) =
                    make_float2(acc[mt][nt][2], acc[mt][nt][3]);
        }
    }

    // ---- fused attention coefficient dots ----
    if (L == 1) {
        float pes[2][2][2], ped[2][2][2];
#pragma unroll
        for (int a0 = 0; a0 < 2; a0++)
#pragma unroll
            for (int a1 = 0; a1 < 2; a1++)
#pragma unroll
                for (int a2 = 0; a2 < 2; a2++) { pes[a0][a1][a2] = 0.f; ped[a0][a1][a2] = 0.f; }
#pragma unroll
        for (int nt = 0; nt < 8; nt++) {
            int colg = col0 + warpN * 64 + nt * 8 + (lane & 3) * 2;
            float a0s = __ldg(asrc + colg), a1s = __ldg(asrc + colg + 1);
            float a0d = __ldg(adst + colg), a1d = __ldg(adst + colg + 1);
            int hb = nt >> 2;
#pragma unroll
            for (int mt = 0; mt < 2; mt++) {
                pes[mt][0][hb] += acc[mt][nt][0] * a0s + acc[mt][nt][1] * a1s;
                pes[mt][1][hb] += acc[mt][nt][2] * a0s + acc[mt][nt][3] * a1s;
                ped[mt][0][hb] += acc[mt][nt][0] * a0d + acc[mt][nt][1] * a1d;
                ped[mt][1][hb] += acc[mt][nt][2] * a0d + acc[mt][nt][3] * a1d;
            }
        }
#pragma unroll
        for (int a0 = 0; a0 < 2; a0++)
#pragma unroll
            for (int a1 = 0; a1 < 2; a1++)
#pragma unroll
                for (int a2 = 0; a2 < 2; a2++) {
                    pes[a0][a1][a2] += __shfl_xor_sync(0xFFFFFFFFu, pes[a0][a1][a2], 1);
                    pes[a0][a1][a2] += __shfl_xor_sync(0xFFFFFFFFu, pes[a0][a1][a2], 2);
                    ped[a0][a1][a2] += __shfl_xor_sync(0xFFFFFFFFu, ped[a0][a1][a2], 1);
                    ped[a0][a1][a2] += __shfl_xor_sync(0xFFFFFFFFu, ped[a0][a1][a2], 2);
                }
        if ((lane & 3) == 0) {
#pragma unroll
            for (int mt = 0; mt < 2; mt++)
#pragma unroll
                for (int rs = 0; rs < 2; rs++) {
                    int node = row0 + warpM * 32 + mt * 16 + (lane >> 2) + rs * 8;
                    if (node < NN) {
#pragma unroll
                        for (int hb = 0; hb < 2; hb++) {
                            int head = blockIdx.x * 4 + warpN * 2 + hb;
                            g_es1[node * 8 + head] = pes[mt][rs][hb];
                            g_ed1[node * 8 + head] = ped[mt][rs][hb];
                        }
                    }
                }
        }
    } else {
        float pes[2][2], ped[2][2];
#pragma unroll
        for (int a0 = 0; a0 < 2; a0++)
#pragma unroll
            for (int a1 = 0; a1 < 2; a1++) { pes[a0][a1] = 0.f; ped[a0][a1] = 0.f; }
#pragma unroll
        for (int nt = 0; nt < 8; nt++) {
            int colg = col0 + warpN * 64 + nt * 8 + (lane & 3) * 2;
            float a0s = __ldg(asrc + colg), a1s = __ldg(asrc + colg + 1);
            float a0d = __ldg(adst + colg), a1d = __ldg(adst + colg + 1);
#pragma unroll
            for (int mt = 0; mt < 2; mt++) {
                pes[mt][0] += acc[mt][nt][0] * a0s + acc[mt][nt][1] * a1s;
                pes[mt][1] += acc[mt][nt][2] * a0s + acc[mt][nt][3] * a1s;
                ped[mt][0] += acc[mt][nt][0] * a0d + acc[mt][nt][1] * a1d;
                ped[mt][1] += acc[mt][nt][2] * a0d + acc[mt][nt][3] * a1d;
            }
        }
#pragma unroll
        for (int a0 = 0; a0 < 2; a0++)
#pragma unroll
            for (int a1 = 0; a1 < 2; a1++) {
                pes[a0][a1] += __shfl_xor_sync(0xFFFFFFFFu, pes[a0][a1], 1);
                pes[a0][a1] += __shfl_xor_sync(0xFFFFFFFFu, pes[a0][a1], 2);
                ped[a0][a1] += __shfl_xor_sync(0xFFFFFFFFu, ped[a0][a1], 1);
                ped[a0][a1] += __shfl_xor_sync(0xFFFFFFFFu, ped[a0][a1], 2);
            }
        if ((lane & 3) == 0) {
#pragma unroll
            for (int mt = 0; mt < 2; mt++)
#pragma unroll
                for (int rs = 0; rs < 2; rs++) {
                    int node = row0 + warpM * 32 + mt * 16 + (lane >> 2) + rs * 8;
                    if (node < NN) {
                        atomicAdd(&g_es2[node], pes[mt][rs]);
                        atomicAdd(&g_ed2[node], ped[mt][rs]);
                    }
                }
        }
    }
}

// ---------------- per-edge exp weights (no max subtraction: e in safe range) ----------------
__global__ void k_w1() {
    int i = blockIdx.x * blockDim.x + threadIdx.x;
    if (i >= ET) return;
    int sc = g_srcl[i], dn = g_dstl[i];
    float4 e0 = *(const float4*)(g_es1 + sc * 8);
    float4 e1 = *(const float4*)(g_es1 + sc * 8 + 4);
    float4 d0 = *(const float4*)(g_ed1 + dn * 8);
    float4 d1 = *(const float4*)(g_ed1 + dn * 8 + 4);
    float4 w0, w1;
    w0.x = __expf(lrelu(e0.x + d0.x));
    w0.y = __expf(lrelu(e0.y + d0.y));
    w0.z = __expf(lrelu(e0.z + d0.z));
    w0.w = __expf(lrelu(e0.w + d0.w));
    w1.x = __expf(lrelu(e1.x + d1.x));
    w1.y = __expf(lrelu(e1.y + d1.y));
    w1.z = __expf(lrelu(e1.z + d1.z));
    w1.w = __expf(lrelu(e1.w + d1.w));
    *(float4*)(g_w1 + (size_t)i * 8)     = w0;
    *(float4*)(g_w1 + (size_t)i * 8 + 4) = w1;
}

__global__ void k_w2() {
    int i = blockIdx.x * blockDim.x + threadIdx.x;
    if (i >= ET) return;
    g_w2[i] = __expf(lrelu(g_es2[g_srcl[i]] + g_ed2[g_dstl[i]]));
}

// ---------------- GAT layer 1: warp per destination node, single fused pass ----------------
__global__ void k_gat1(const float* __restrict__ b1) {
    int n = (blockIdx.x * blockDim.x + threadIdx.x) >> 5;
    int lane = threadIdx.x & 31;
    if (n >= NN) return;
    int beg = g_off[n], end = g_off[n + 1];

    float s[HH], acc[HH];
#pragma unroll
    for (int j = 0; j < HH; j++) { s[j] = 0.f; acc[j] = 0.f; }

#pragma unroll 2
    for (int i = beg; i < end; i++) {
        int sc = g_srcl[i];
        const float* hrow = g_h1 + (size_t)sc * DD;
        const float* wr = g_w1 + (size_t)i * 8;
#pragma unroll
        for (int j = 0; j < HH; j++) {
            float w = wr[j];
            s[j] += w;
            acc[j] = fmaf(w, hrow[j * CC + lane], acc[j]);
        }
    }
#pragma unroll
    for (int j = 0; j < HH; j++) {
        float v = acc[j] / (s[j] + 1e-16f) + b1[j * CC + lane];
        v = v > 0.f ? v : expm1f(v);  // ELU
        g_act[(size_t)n * DD + j * CC + lane] = v;
    }
}

// ---------------- GAT layer 2 (H=1, C=256): warp per destination node ----------------
__global__ void k_gat2(const float* __restrict__ b2, float* __restrict__ out) {
    int n = (blockIdx.x * blockDim.x + threadIdx.x) >> 5;
    int lane = threadIdx.x & 31;
    if (n >= NN) return;
    int beg = g_off[n], end = g_off[n + 1];

    float s = 0.f;
    float acc[8];
#pragma unroll
    for (int j = 0; j < 8; j++) acc[j] = 0.f;

#pragma unroll 2
    for (int i = beg; i < end; i++) {
        int sc = g_srcl[i];
        float w = g_w2[i];
        s += w;
        const float* hrow = g_h2 + (size_t)sc * DD;
#pragma unroll
        for (int j = 0; j < 8; j++)
            acc[j] = fmaf(w, hrow[j * 32 + lane], acc[j]);
    }
    float inv = 1.f / (s + 1e-16f);
#pragma unroll
    for (int j = 0; j < 8; j++)
        out[(size_t)n * DD + j * 32 + lane] = acc[j] * inv + b2[j * 32 + lane];
}

// ---------------- launch ----------------
#define SMEM_GEMM 81920

extern "C" void kernel_launch(void* const* d_in, const int* in_sizes, int n_in,
                              void* d_out, int out_size) {
    const float* x      = (const float*)d_in[0];
    const int*   ei     = (const int*)d_in[1];
    const float* W1     = (const float*)d_in[2];
    const float* a_src1 = (const float*)d_in[3];
    const float* a_dst1 = (const float*)d_in[4];
    const float* b1     = (const float*)d_in[5];
    const float* W2     = (const float*)d_in[6];
    const float* a_src2 = (const float*)d_in[7];
    const float* a_dst2 = (const float*)d_in[8];
    const float* b2     = (const float*)d_in[9];
    float* out = (float*)d_out;

    cudaFuncSetAttribute(k_gemm_mma<1>, cudaFuncAttributeMaxDynamicSharedMemorySize, SMEM_GEMM);
    cudaFuncSetAttribute(k_gemm_mma<2>, cudaFuncAttributeMaxDynamicSharedMemorySize, SMEM_GEMM);

    dim3 gdim(2, (NN + 127) / 128);
    int warp_grid = (NN * 32 + 255) / 256;
    int edge_grid = (ET + 255) / 256;
    cudaStream_t s0 = (cudaStream_t)0;

    // try fork-join: CSR build on side stream, prepB+GEMM1 on main stream
    cudaStream_t s1 = 0;
    cudaEvent_t ef = 0, ej = 0;
    bool fork = (cudaStreamCreateWithFlags(&s1, cudaStreamNonBlocking) == cudaSuccess) &&
                (cudaEventCreateWithFlags(&ef, cudaEventDisableTiming) == cudaSuccess) &&
                (cudaEventCreateWithFlags(&ej, cudaEventDisableTiming) == cudaSuccess);

    cudaStream_t sc = fork ? s1 : s0;
    if (fork) {
        cudaEventRecord(ef, s0);
        cudaStreamWaitEvent(s1, ef, 0);
    }

    // CSR chain (side stream when forked)
    k_zero<<<(NN + 255) / 256, 256, 0, sc>>>();
    k_count<<<(ET + 255) / 256, 256, 0, sc>>>(ei);
    k_scan1<<<NBL, SCB, 0, sc>>>();
    k_scan2<<<1, 128, 0, sc>>>();
    k_scan3<<<NBL, SCB, 0, sc>>>();
    k_scatter<<<(ET + 255) / 256, 256, 0, sc>>>(ei);
    if (fork) cudaEventRecord(ej, s1);

    // main chain: weight prep + GEMM1 (independent of CSR)
    k_prepB<<<(256 * 128 + 256 * 256 + 255) / 256, 256, 0, s0>>>(W1, W2);
    k_gemm_mma<1><<<gdim, 256, SMEM_GEMM, s0>>>(x, a_src1, a_dst1);

    if (fork) cudaStreamWaitEvent(s0, ej, 0);

    // join: edge weights + layer1 aggregate
    k_w1<<<edge_grid, 256, 0, s0>>>();
    k_gat1<<<warp_grid, 256, 0, s0>>>(b1);

    // layer 2
    k_gemm_mma<2><<<gdim, 256, SMEM_GEMM, s0>>>(nullptr, a_src2, a_dst2);
    k_w2<<<edge_grid, 256, 0, s0>>>();
    k_gat2<<<warp_grid, 256, 0, s0>>>(b2, out);

    // cleanup only when not capturing (capture call leaks 1 stream + 2 events, once)
    cudaStreamCaptureStatus cs = cudaStreamCaptureStatusNone;
    cudaStreamIsCapturing(s0, &cs);
    if (fork && cs == cudaStreamCaptureStatusNone) {
        cudaStreamDestroy(s1);
        cudaEventDestroy(ef);
        cudaEventDestroy(ej);
    }
}

// round 8
// speedup vs baseline: 1.9025x; 1.0445x over previous
#include <cuda_runtime.h>
#include <cuda_bf16.h>
#include <math.h>

#define NN 50000
#define NE 500000
#define ET (NE + NN)   /* edges + self loops = 550000 */
#define DIN 128
#define DD 256
#define HH 8
#define CC 32

// ---------------- scratch (static device globals; no allocation) ----------------
__device__ float g_h1[(size_t)NN * DD];   // layer1 GEMM out  [N,256]
__device__ float g_act[(size_t)NN * DD];  // elu(gat1 out)    [N,256]
__device__ float g_h2[(size_t)NN * DD];   // layer2 GEMM out  [N,256]
__device__ float g_es1[NN * HH];
__device__ float g_ed1[NN * HH];
__device__ float g_es2[NN];
__device__ float g_ed2[NN];
__device__ int   g_cnt[NN];
__device__ int   g_off[NN + 1];
__device__ int   g_cur[NN];
__device__ int   g_srcl[ET];
__device__ int   g_dstl[ET];
__device__ float g_w1[(size_t)ET * HH];   // per-edge exp weights, layer1
__device__ float g_w2[ET];                // per-edge exp weights, layer2
#define SCB 512
#define NBL ((NN + SCB - 1) / SCB)   /* 98 */
__device__ int   g_bsum[NBL];
// transposed + bf16-split weights: Bt[n][k] = W[k][n]
__device__ __nv_bfloat16 g_bt1h[256 * 128];
__device__ __nv_bfloat16 g_bt1l[256 * 128];
__device__ __nv_bfloat16 g_bt2h[256 * 256];
__device__ __nv_bfloat16 g_bt2l[256 * 256];

// ---------------- helpers ----------------
__device__ __forceinline__ void cvt2(float a, float b, unsigned& hi, unsigned& lo) {
    __nv_bfloat16 ah = __float2bfloat16_rn(a), bh = __float2bfloat16_rn(b);
    float al = a - __bfloat162float(ah), bl = b - __bfloat162float(bh);
    __nv_bfloat16 alh = __float2bfloat16_rn(al), blh = __float2bfloat16_rn(bl);
    unsigned short au = *(unsigned short*)&ah, bu = *(unsigned short*)&bh;
    unsigned short alu = *(unsigned short*)&alh, blu = *(unsigned short*)&blh;
    hi = (unsigned)au | ((unsigned)bu << 16);
    lo = (unsigned)alu | ((unsigned)blu << 16);
}

__device__ __forceinline__ void mma16816(float* c, const unsigned* a, unsigned b0, unsigned b1) {
    asm volatile(
        "mma.sync.aligned.m16n8k16.row.col.f32.bf16.bf16.f32 "
        "{%0,%1,%2,%3}, {%4,%5,%6,%7}, {%8,%9}, {%0,%1,%2,%3};"
        : "+f"(c[0]), "+f"(c[1]), "+f"(c[2]), "+f"(c[3])
        : "r"(a[0]), "r"(a[1]), "r"(a[2]), "r"(a[3]), "r"(b0), "r"(b1));
}

__device__ __forceinline__ void ldsm_x4(unsigned* r, unsigned addr) {
    asm volatile("ldmatrix.sync.aligned.m8n8.x4.shared.b16 {%0,%1,%2,%3}, [%4];"
                 : "=r"(r[0]), "=r"(r[1]), "=r"(r[2]), "=r"(r[3]) : "r"(addr));
}

__device__ __forceinline__ float lrelu(float e) { return e > 0.f ? e : 0.2f * e; }

// ---------------- CSR build ----------------
__global__ void k_zero() {
    int i = blockIdx.x * blockDim.x + threadIdx.x;
    if (i < NN) { g_cnt[i] = 0; g_es2[i] = 0.f; g_ed2[i] = 0.f; }
}

__global__ void k_count(const int* __restrict__ ei) {
    int t = blockIdx.x * blockDim.x + threadIdx.x;
    if (t >= ET) return;
    int dst = (t < NE) ? ei[NE + t] : (t - NE);
    atomicAdd(&g_cnt[dst], 1);
}

__global__ void k_scan1() {
    __shared__ int wsum[16];
    int t = threadIdx.x;
    int i = blockIdx.x * SCB + t;
    int v = (i < NN) ? g_cnt[i] : 0;
#pragma unroll
    for (int o = 16; o; o >>= 1) v += __shfl_xor_sync(0xFFFFFFFFu, v, o);
    if ((t & 31) == 0) wsum[t >> 5] = v;
    __syncthreads();
    if (t < 16) {
        int s = wsum[t];
#pragma unroll
        for (int o = 8; o; o >>= 1) s += __shfl_xor_sync(0xFFFFu, s, o);
        if (t == 0) g_bsum[blockIdx.x] = s;
    }
}

__global__ void k_scan2() {
    __shared__ int s[128];
    int t = threadIdx.x;
    int v = (t < NBL) ? g_bsum[t] : 0;
    s[t] = v;
    __syncthreads();
#pragma unroll
    for (int d = 1; d < 128; d <<= 1) {
        int u = (t >= d) ? s[t - d] : 0;
        __syncthreads();
        s[t] += u;
        __syncthreads();
    }
    if (t < NBL) g_bsum[t] = s[t] - v;   // exclusive
    if (t == 0) g_off[NN] = ET;
}

__global__ void k_scan3() {
    __shared__ int s[SCB];
    int t = threadIdx.x;
    int i = blockIdx.x * SCB + t;
    int v = (i < NN) ? g_cnt[i] : 0;
    s[t] = v;
    __syncthreads();
#pragma unroll
    for (int d = 1; d < SCB; d <<= 1) {
        int u = (t >= d) ? s[t - d] : 0;
        __syncthreads();
        s[t] += u;
        __syncthreads();
    }
    if (i < NN) {
        int e = s[t] - v + g_bsum[blockIdx.x];
        g_off[i] = e;
        g_cur[i] = e;
    }
}

__global__ void k_scatter(const int* __restrict__ ei) {
    int t = blockIdx.x * blockDim.x + threadIdx.x;
    if (t >= ET) return;
    int src, dst;
    if (t < NE) { src = ei[t]; dst = ei[NE + t]; }
    else        { src = t - NE; dst = t - NE; }
    int pos = atomicAdd(&g_cur[dst], 1);
    g_srcl[pos] = src;
    g_dstl[pos] = dst;
}

// ---------------- weight prep: transpose + bf16 split ----------------
__global__ void k_prepB(const float* __restrict__ W1, const float* __restrict__ W2) {
    int t = blockIdx.x * blockDim.x + threadIdx.x;
    if (t < 256 * 128) {
        int n = t >> 7, k = t & 127;
        float v = W1[k * 256 + n];
        __nv_bfloat16 h = __float2bfloat16_rn(v);
        g_bt1h[n * 128 + k] = h;
        g_bt1l[n * 128 + k] = __float2bfloat16_rn(v - __bfloat162float(h));
    }
    int t2 = t - 256 * 128;
    if (t2 >= 0 && t2 < 256 * 256) {
        int n = t2 >> 8, k = t2 & 255;
        float v = W2[k * 256 + n];
        __nv_bfloat16 h = __float2bfloat16_rn(v);
        g_bt2h[n * 256 + k] = h;
        g_bt2l[n * 256 + k] = __float2bfloat16_rn(v - __bfloat162float(h));
    }
}

// ---------------- HMMA GEMM, double-buffered, ldmatrix frags, fused attn dots -------
#define SROW 40
#define BUFSZ 40960
#define PLANE 10240

template <int L>
__global__ __launch_bounds__(256)
void k_gemm_mma(const float* __restrict__ Ain,
                const float* __restrict__ asrc, const float* __restrict__ adst) {
    constexpr int KD = (L == 1) ? 128 : 256;
    constexpr int NCH = KD / 32;
    const float* A = (L == 1) ? Ain : g_act;
    float* Cc = (L == 1) ? g_h1 : g_h2;
    const __nv_bfloat16* Bh = (L == 1) ? g_bt1h : g_bt2h;
    const __nv_bfloat16* Bl = (L == 1) ? g_bt1l : g_bt2l;

    extern __shared__ char smem[];
    unsigned sbase = (unsigned)__cvta_generic_to_shared(smem);

    int tid = threadIdx.x, wid = tid >> 5, lane = tid & 31;
    int warpM = wid >> 1, warpN = wid & 1;       // 4 x 2 warp grid
    int row0 = blockIdx.y * 128, col0 = blockIdx.x * 128;

    int ar = tid >> 1, ahalf = tid & 1;
    int agr = row0 + ar;
    bool av = agr < NN;
    const float* arowb = A + (size_t)agr * KD + ahalf * 16;

    // ldmatrix lane geometry
    int g = lane >> 3, ri = lane & 7;
    int a_row = warpM * 32 + ((g & 1) ? 8 : 0) + ri;       // + mt*16 later
    int a_colx = (g & 2) ? 8 : 0;                          // + kt*16
    int b_row = warpN * 64 + ((g & 2) ? 8 : 0) + ri;       // + ntp*16
    int b_colx = (g & 1) ? 8 : 0;                          // + kt*16

    float acc[2][8][4];
#pragma unroll
    for (int mt = 0; mt < 2; mt++)
#pragma unroll
        for (int nt = 0; nt < 8; nt++)
#pragma unroll
            for (int q = 0; q < 4; q++) acc[mt][nt][q] = 0.f;

    float4 pa[4];
    uint4  pb[4];

    // ---- load + stage chunk 0 into buffer 0 ----
    {
        const float* p = arowb;
#pragma unroll
        for (int gg = 0; gg < 4; gg++)
            pa[gg] = av ? *(const float4*)(p + gg * 4) : make_float4(0.f, 0.f, 0.f, 0.f);
#pragma unroll
        for (int it = 0; it < 4; it++) {
            int seg = tid * 4 + it;
            int buf = seg >> 9, s = seg & 511;
            int n = s >> 2, sg = s & 3;
            const __nv_bfloat16* src = (buf ? Bl : Bh) + (size_t)(col0 + n) * KD + sg * 8;
            pb[it] = *(const uint4*)src;
        }
        uint4 hi4[2], lo4[2];
#pragma unroll
        for (int gg = 0; gg < 2; gg++) {
            float4 f0 = pa[gg * 2], f1 = pa[gg * 2 + 1];
            cvt2(f0.x, f0.y, hi4[gg].x, lo4[gg].x);
            cvt2(f0.z, f0.w, hi4[gg].y, lo4[gg].y);
            cvt2(f1.x, f1.y, hi4[gg].z, lo4[gg].z);
            cvt2(f1.z, f1.w, hi4[gg].w, lo4[gg].w);
        }
        char* dh = smem + ar * 80 + ahalf * 32;
        *(uint4*)(dh)              = hi4[0];
        *(uint4*)(dh + 16)         = hi4[1];
        *(uint4*)(dh + PLANE)      = lo4[0];
        *(uint4*)(dh + PLANE + 16) = lo4[1];
#pragma unroll
        for (int it = 0; it < 4; it++) {
            int seg = tid * 4 + it;
            int buf = seg >> 9, s = seg & 511;
            int n = s >> 2, sg = s & 3;
            *(uint4*)(smem + 20480 + buf * PLANE + n * 80 + sg * 16) = pb[it];
        }
    }
    __syncthreads();

    for (int ch = 0; ch < NCH; ch++) {
        // ---- prefetch next chunk's globals (latency covered by MMA below) ----
        if (ch + 1 < NCH) {
            const float* p = arowb + (ch + 1) * 32;
#pragma unroll
            for (int gg = 0; gg < 4; gg++)
                pa[gg] = av ? *(const float4*)(p + gg * 4) : make_float4(0.f, 0.f, 0.f, 0.f);
#pragma unroll
            for (int it = 0; it < 4; it++) {
                int seg = tid * 4 + it;
                int buf = seg >> 9, s = seg & 511;
                int n = s >> 2, sg = s & 3;
                const __nv_bfloat16* src = (buf ? Bl : Bh) + (size_t)(col0 + n) * KD + (ch + 1) * 32 + sg * 8;
                pb[it] = *(const uint4*)src;
            }
        }
        // ---- MMA on current buffer (ldmatrix fragment loads) ----
        {
            unsigned aHb = sbase + (unsigned)((ch & 1) * BUFSZ);
            unsigned aLb = aHb + PLANE;
            unsigned bHb = aHb + 20480;
            unsigned bLb = aHb + 30720;
#pragma unroll
            for (int kt = 0; kt < 2; kt++) {
                int acol = kt * 16 + a_colx;
                int bcol = kt * 16 + b_colx;
                unsigned aH[2][4], aL[2][4];
#pragma unroll
                for (int mt = 0; mt < 2; mt++) {
                    unsigned off = (unsigned)((a_row + mt * 16) * SROW + acol) * 2u;
                    ldsm_x4(aH[mt], aHb + off);
                    ldsm_x4(aL[mt], aLb + off);
                }
#pragma unroll
                for (int ntp = 0; ntp < 4; ntp++) {
                    unsigned off = (unsigned)((b_row + ntp * 16) * SROW + bcol) * 2u;
                    unsigned bH4[4], bL4[4];
                    ldsm_x4(bH4, bHb + off);
                    ldsm_x4(bL4, bLb + off);
#pragma unroll
                    for (int h = 0; h < 2; h++) {
                        int nt = ntp * 2 + h;
                        unsigned bH0 = bH4[h * 2], bH1 = bH4[h * 2 + 1];
                        unsigned bL0 = bL4[h * 2], bL1 = bL4[h * 2 + 1];
                        mma16816(acc[0][nt], aH[0], bH0, bH1);
                        mma16816(acc[1][nt], aH[1], bH0, bH1);
                        mma16816(acc[0][nt], aH[0], bL0, bL1);
                        mma16816(acc[1][nt], aH[1], bL0, bL1);
                        mma16816(acc[0][nt], aL[0], bH0, bH1);
                        mma16816(acc[1][nt], aL[1], bH0, bH1);
                    }
                }
            }
        }
        // ---- stage next chunk into the other buffer ----
        if (ch + 1 < NCH) {
            char* base = smem + ((ch + 1) & 1) * BUFSZ;
            uint4 hi4[2], lo4[2];
#pragma unroll
            for (int gg = 0; gg < 2; gg++) {
                float4 f0 = pa[gg * 2], f1 = pa[gg * 2 + 1];
                cvt2(f0.x, f0.y, hi4[gg].x, lo4[gg].x);
                cvt2(f0.z, f0.w, hi4[gg].y, lo4[gg].y);
                cvt2(f1.x, f1.y, hi4[gg].z, lo4[gg].z);
                cvt2(f1.z, f1.w, hi4[gg].w, lo4[gg].w);
            }
            char* dh = base + ar * 80 + ahalf * 32;
            *(uint4*)(dh)              = hi4[0];
            *(uint4*)(dh + 16)         = hi4[1];
            *(uint4*)(dh + PLANE)      = lo4[0];
            *(uint4*)(dh + PLANE + 16) = lo4[1];
#pragma unroll
            for (int it = 0; it < 4; it++) {
                int seg = tid * 4 + it;
                int buf = seg >> 9, s = seg & 511;
                int n = s >> 2, sg = s & 3;
                *(uint4*)(base + 20480 + buf * PLANE + n * 80 + sg * 16) = pb[it];
            }
        }
        __syncthreads();
    }

    // ---- epilogue: store C ----
#pragma unroll
    for (int mt = 0; mt < 2; mt++) {
        int r_lo = row0 + warpM * 32 + mt * 16 + (lane >> 2);
        int cc = col0 + warpN * 64 + (lane & 3) * 2;
#pragma unroll
        for (int nt = 0; nt < 8; nt++) {
            if (r_lo < NN)
                *(float2*)(Cc + (size_t)r_lo * DD + cc + nt * 8) =
                    make_float2(acc[mt][nt][0], acc[mt][nt][1]);
            if (r_lo + 8 < NN)
                *(float2*)(Cc + (size_t)(r_lo + 8) * DD + cc + nt * 8) =
                    make_float2(acc[mt][nt][2], acc[mt][nt][3]);
        }
    }

    // ---- fused attention coefficient dots ----
    if (L == 1) {
        float pes[2][2][2], ped[2][2][2];
#pragma unroll
        for (int a0 = 0; a0 < 2; a0++)
#pragma unroll
            for (int a1 = 0; a1 < 2; a1++)
#pragma unroll
                for (int a2 = 0; a2 < 2; a2++) { pes[a0][a1][a2] = 0.f; ped[a0][a1][a2] = 0.f; }
#pragma unroll
        for (int nt = 0; nt < 8; nt++) {
            int colg = col0 + warpN * 64 + nt * 8 + (lane & 3) * 2;
            float a0s = __ldg(asrc + colg), a1s = __ldg(asrc + colg + 1);
            float a0d = __ldg(adst + colg), a1d = __ldg(adst + colg + 1);
            int hb = nt >> 2;
#pragma unroll
            for (int mt = 0; mt < 2; mt++) {
                pes[mt][0][hb] += acc[mt][nt][0] * a0s + acc[mt][nt][1] * a1s;
                pes[mt][1][hb] += acc[mt][nt][2] * a0s + acc[mt][nt][3] * a1s;
                ped[mt][0][hb] += acc[mt][nt][0] * a0d + acc[mt][nt][1] * a1d;
                ped[mt][1][hb] += acc[mt][nt][2] * a0d + acc[mt][nt][3] * a1d;
            }
        }
#pragma unroll
        for (int a0 = 0; a0 < 2; a0++)
#pragma unroll
            for (int a1 = 0; a1 < 2; a1++)
#pragma unroll
                for (int a2 = 0; a2 < 2; a2++) {
                    pes[a0][a1][a2] += __shfl_xor_sync(0xFFFFFFFFu, pes[a0][a1][a2], 1);
                    pes[a0][a1][a2] += __shfl_xor_sync(0xFFFFFFFFu, pes[a0][a1][a2], 2);
                    ped[a0][a1][a2] += __shfl_xor_sync(0xFFFFFFFFu, ped[a0][a1][a2], 1);
                    ped[a0][a1][a2] += __shfl_xor_sync(0xFFFFFFFFu, ped[a0][a1][a2], 2);
                }
        if ((lane & 3) == 0) {
#pragma unroll
            for (int mt = 0; mt < 2; mt++)
#pragma unroll
                for (int rs = 0; rs < 2; rs++) {
                    int node = row0 + warpM * 32 + mt * 16 + (lane >> 2) + rs * 8;
                    if (node < NN) {
#pragma unroll
                        for (int hb = 0; hb < 2; hb++) {
                            int head = blockIdx.x * 4 + warpN * 2 + hb;
                            g_es1[node * 8 + head] = pes[mt][rs][hb];
                            g_ed1[node * 8 + head] = ped[mt][rs][hb];
                        }
                    }
                }
        }
    } else {
        float pes[2][2], ped[2][2];
#pragma unroll
        for (int a0 = 0; a0 < 2; a0++)
#pragma unroll
            for (int a1 = 0; a1 < 2; a1++) { pes[a0][a1] = 0.f; ped[a0][a1] = 0.f; }
#pragma unroll
        for (int nt = 0; nt < 8; nt++) {
            int colg = col0 + warpN * 64 + nt * 8 + (lane & 3) * 2;
            float a0s = __ldg(asrc + colg), a1s = __ldg(asrc + colg + 1);
            float a0d = __ldg(adst + colg), a1d = __ldg(adst + colg + 1);
#pragma unroll
            for (int mt = 0; mt < 2; mt++) {
                pes[mt][0] += acc[mt][nt][0] * a0s + acc[mt][nt][1] * a1s;
                pes[mt][1] += acc[mt][nt][2] * a0s + acc[mt][nt][3] * a1s;
                ped[mt][0] += acc[mt][nt][0] * a0d + acc[mt][nt][1] * a1d;
                ped[mt][1] += acc[mt][nt][2] * a0d + acc[mt][nt][3] * a1d;
            }
        }
#pragma unroll
        for (int a0 = 0; a0 < 2; a0++)
#pragma unroll
            for (int a1 = 0; a1 < 2; a1++) {
                pes[a0][a1] += __shfl_xor_sync(0xFFFFFFFFu, pes[a0][a1], 1);
                pes[a0][a1] += __shfl_xor_sync(0xFFFFFFFFu, pes[a0][a1], 2);
                ped[a0][a1] += __shfl_xor_sync(0xFFFFFFFFu, ped[a0][a1], 1);
                ped[a0][a1] += __shfl_xor_sync(0xFFFFFFFFu, ped[a0][a1], 2);
            }
        if ((lane & 3) == 0) {
#pragma unroll
            for (int mt = 0; mt < 2; mt++)
#pragma unroll
                for (int rs = 0; rs < 2; rs++) {
                    int node = row0 + warpM * 32 + mt * 16 + (lane >> 2) + rs * 8;
                    if (node < NN) {
                        atomicAdd(&g_es2[node], pes[mt][rs]);
                        atomicAdd(&g_ed2[node], ped[mt][rs]);
                    }
                }
        }
    }
}

// ---------------- per-edge exp weights (no max subtraction: e in safe range) ----------------
__global__ void k_w1() {
    int i = blockIdx.x * blockDim.x + threadIdx.x;
    if (i >= ET) return;
    int sc = g_srcl[i], dn = g_dstl[i];
    float4 e0 = *(const float4*)(g_es1 + sc * 8);
    float4 e1 = *(const float4*)(g_es1 + sc * 8 + 4);
    float4 d0 = *(const float4*)(g_ed1 + dn * 8);
    float4 d1 = *(const float4*)(g_ed1 + dn * 8 + 4);
    float4 w0, w1;
    w0.x = __expf(lrelu(e0.x + d0.x));
    w0.y = __expf(lrelu(e0.y + d0.y));
    w0.z = __expf(lrelu(e0.z + d0.z));
    w0.w = __expf(lrelu(e0.w + d0.w));
    w1.x = __expf(lrelu(e1.x + d1.x));
    w1.y = __expf(lrelu(e1.y + d1.y));
    w1.z = __expf(lrelu(e1.z + d1.z));
    w1.w = __expf(lrelu(e1.w + d1.w));
    *(float4*)(g_w1 + (size_t)i * 8)     = w0;
    *(float4*)(g_w1 + (size_t)i * 8 + 4) = w1;
}

__global__ void k_w2() {
    int i = blockIdx.x * blockDim.x + threadIdx.x;
    if (i >= ET) return;
    g_w2[i] = __expf(lrelu(g_es2[g_srcl[i]] + g_ed2[g_dstl[i]]));
}

// ---------------- GAT layer 1: warp per dst node; lane owns 8 cols of one head ----------------
__global__ void k_gat1(const float* __restrict__ b1) {
    int n = (blockIdx.x * blockDim.x + threadIdx.x) >> 5;
    int lane = threadIdx.x & 31;
    if (n >= NN) return;
    int beg = g_off[n], end = g_off[n + 1];
    int col = lane * 8;           // cols [col, col+8) all in head col>>5 = lane>>2
    int head = lane >> 2;

    float s = 0.f;
    float acc[8];
#pragma unroll
    for (int q = 0; q < 8; q++) acc[q] = 0.f;

#pragma unroll 4
    for (int i = beg; i < end; i++) {
        int sc = g_srcl[i];
        float w = g_w1[(size_t)i * 8 + head];
        const float* hrow = g_h1 + (size_t)sc * DD + col;
        float4 h0 = *(const float4*)(hrow);
        float4 h1 = *(const float4*)(hrow + 4);
        s += w;
        acc[0] = fmaf(w, h0.x, acc[0]);
        acc[1] = fmaf(w, h0.y, acc[1]);
        acc[2] = fmaf(w, h0.z, acc[2]);
        acc[3] = fmaf(w, h0.w, acc[3]);
        acc[4] = fmaf(w, h1.x, acc[4]);
        acc[5] = fmaf(w, h1.y, acc[5]);
        acc[6] = fmaf(w, h1.z, acc[6]);
        acc[7] = fmaf(w, h1.w, acc[7]);
    }
    float inv = 1.f / (s + 1e-16f);
    float res[8];
#pragma unroll
    for (int q = 0; q < 8; q++) {
        float v = acc[q] * inv + b1[col + q];
        res[q] = v > 0.f ? v : expm1f(v);  // ELU
    }
    float4 o0 = make_float4(res[0], res[1], res[2], res[3]);
    float4 o1 = make_float4(res[4], res[5], res[6], res[7]);
    float* dst = g_act + (size_t)n * DD + col;
    *(float4*)(dst)     = o0;
    *(float4*)(dst + 4) = o1;
}

// ---------------- GAT layer 2 (H=1, C=256): warp per dst node, lane owns 8 cols -------------
__global__ void k_gat2(const float* __restrict__ b2, float* __restrict__ out) {
    int n = (blockIdx.x * blockDim.x + threadIdx.x) >> 5;
    int lane = threadIdx.x & 31;
    if (n >= NN) return;
    int beg = g_off[n], end = g_off[n + 1];
    int col = lane * 8;

    float s = 0.f;
    float acc[8];
#pragma unroll
    for (int q = 0; q < 8; q++) acc[q] = 0.f;

#pragma unroll 4
    for (int i = beg; i < end; i++) {
        int sc = g_srcl[i];
        float w = g_w2[i];
        const float* hrow = g_h2 + (size_t)sc * DD + col;
        float4 h0 = *(const float4*)(hrow);
        float4 h1 = *(const float4*)(hrow + 4);
        s += w;
        acc[0] = fmaf(w, h0.x, acc[0]);
        acc[1] = fmaf(w, h0.y, acc[1]);
        acc[2] = fmaf(w, h0.z, acc[2]);
        acc[3] = fmaf(w, h0.w, acc[3]);
        acc[4] = fmaf(w, h1.x, acc[4]);
        acc[5] = fmaf(w, h1.y, acc[5]);
        acc[6] = fmaf(w, h1.z, acc[6]);
        acc[7] = fmaf(w, h1.w, acc[7]);
    }
    float inv = 1.f / (s + 1e-16f);
    float4 o0 = make_float4(acc[0] * inv + b2[col],     acc[1] * inv + b2[col + 1],
                            acc[2] * inv + b2[col + 2], acc[3] * inv + b2[col + 3]);
    float4 o1 = make_float4(acc[4] * inv + b2[col + 4], acc[5] * inv + b2[col + 5],
                            acc[6] * inv + b2[col + 6], acc[7] * inv + b2[col + 7]);
    float* dst = out + (size_t)n * DD + col;
    *(float4*)(dst)     = o0;
    *(float4*)(dst + 4) = o1;
}

// ---------------- launch ----------------
#define SMEM_GEMM 81920

extern "C" void kernel_launch(void* const* d_in, const int* in_sizes, int n_in,
                              void* d_out, int out_size) {
    const float* x      = (const float*)d_in[0];
    const int*   ei     = (const int*)d_in[1];
    const float* W1     = (const float*)d_in[2];
    const float* a_src1 = (const float*)d_in[3];
    const float* a_dst1 = (const float*)d_in[4];
    const float* b1     = (const float*)d_in[5];
    const float* W2     = (const float*)d_in[6];
    const float* a_src2 = (const float*)d_in[7];
    const float* a_dst2 = (const float*)d_in[8];
    const float* b2     = (const float*)d_in[9];
    float* out = (float*)d_out;

    cudaFuncSetAttribute(k_gemm_mma<1>, cudaFuncAttributeMaxDynamicSharedMemorySize, SMEM_GEMM);
    cudaFuncSetAttribute(k_gemm_mma<2>, cudaFuncAttributeMaxDynamicSharedMemorySize, SMEM_GEMM);

    dim3 gdim(2, (NN + 127) / 128);
    int warp_grid = (NN * 32 + 255) / 256;
    int edge_grid = (ET + 255) / 256;
    cudaStream_t s0 = (cudaStream_t)0;

    // fork-join: CSR build on side stream, prepB+GEMM1 on main stream
    cudaStream_t s1 = 0;
    cudaEvent_t ef = 0, ej = 0;
    bool fork = (cudaStreamCreateWithFlags(&s1, cudaStreamNonBlocking) == cudaSuccess) &&
                (cudaEventCreateWithFlags(&ef, cudaEventDisableTiming) == cudaSuccess) &&
                (cudaEventCreateWithFlags(&ej, cudaEventDisableTiming) == cudaSuccess);

    cudaStream_t sc = fork ? s1 : s0;
    if (fork) {
        cudaEventRecord(ef, s0);
        cudaStreamWaitEvent(s1, ef, 0);
    }

    // CSR chain (side stream when forked)
    k_zero<<<(NN + 255) / 256, 256, 0, sc>>>();
    k_count<<<(ET + 255) / 256, 256, 0, sc>>>(ei);
    k_scan1<<<NBL, SCB, 0, sc>>>();
    k_scan2<<<1, 128, 0, sc>>>();
    k_scan3<<<NBL, SCB, 0, sc>>>();
    k_scatter<<<(ET + 255) / 256, 256, 0, sc>>>(ei);
    if (fork) cudaEventRecord(ej, s1);

    // main chain: weight prep + GEMM1 (independent of CSR)
    k_prepB<<<(256 * 128 + 256 * 256 + 255) / 256, 256, 0, s0>>>(W1, W2);
    k_gemm_mma<1><<<gdim, 256, SMEM_GEMM, s0>>>(x, a_src1, a_dst1);

    if (fork) cudaStreamWaitEvent(s0, ej, 0);

    // join: edge weights + layer1 aggregate
    k_w1<<<edge_grid, 256, 0, s0>>>();
    k_gat1<<<warp_grid, 256, 0, s0>>>(b1);

    // layer 2
    k_gemm_mma<2><<<gdim, 256, SMEM_GEMM, s0>>>(nullptr, a_src2, a_dst2);
    k_w2<<<edge_grid, 256, 0, s0>>>();
    k_gat2<<<warp_grid, 256, 0, s0>>>(b2, out);

    // cleanup only when not capturing (capture call leaks 1 stream + 2 events, once)
    cudaStreamCaptureStatus cs = cudaStreamCaptureStatusNone;
    cudaStreamIsCapturing(s0, &cs);
    if (fork && cs == cudaStreamCaptureStatusNone) {
        cudaStreamDestroy(s1);
        cudaEventDestroy(ef);
        cudaEventDestroy(ej);
    }
}

// round 9
// speedup vs baseline: 1.9734x; 1.0373x over previous
#include <cuda_runtime.h>
#include <cuda_bf16.h>
#include <math.h>

#define NN 50000
#define NE 500000
#define ET (NE + NN)   /* edges + self loops = 550000 */
#define DIN 128
#define DD 256
#define HH 8
#define CC 32

// ---------------- scratch (static device globals; no allocation) ----------------
__device__ float g_h1[(size_t)NN * DD];   // layer1 GEMM out  [N,256]
__device__ float g_act[(size_t)NN * DD];  // elu(gat1 out)    [N,256]
__device__ float g_h2[(size_t)NN * DD];   // layer2 GEMM out  [N,256]
__device__ float g_es1[NN * HH];
__device__ float g_ed1[NN * HH];
__device__ float g_es2[NN];
__device__ float g_ed2[NN];
__device__ int   g_cnt[NN];
__device__ int   g_off[NN + 1];
__device__ int   g_cur[NN];
__device__ int   g_srcl[ET];
#define SCB 512
#define NBL ((NN + SCB - 1) / SCB)   /* 98 */
__device__ int   g_bsum[NBL];
// transposed + bf16-split weights: Bt[n][k] = W[k][n]
__device__ __nv_bfloat16 g_bt1h[256 * 128];
__device__ __nv_bfloat16 g_bt1l[256 * 128];
__device__ __nv_bfloat16 g_bt2h[256 * 256];
__device__ __nv_bfloat16 g_bt2l[256 * 256];

// ---------------- helpers ----------------
__device__ __forceinline__ void cvt2(float a, float b, unsigned& hi, unsigned& lo) {
    __nv_bfloat16 ah = __float2bfloat16_rn(a), bh = __float2bfloat16_rn(b);
    float al = a - __bfloat162float(ah), bl = b - __bfloat162float(bh);
    __nv_bfloat16 alh = __float2bfloat16_rn(al), blh = __float2bfloat16_rn(bl);
    unsigned short au = *(unsigned short*)&ah, bu = *(unsigned short*)&bh;
    unsigned short alu = *(unsigned short*)&alh, blu = *(unsigned short*)&blh;
    hi = (unsigned)au | ((unsigned)bu << 16);
    lo = (unsigned)alu | ((unsigned)blu << 16);
}

__device__ __forceinline__ void mma16816(float* c, const unsigned* a, unsigned b0, unsigned b1) {
    asm volatile(
        "mma.sync.aligned.m16n8k16.row.col.f32.bf16.bf16.f32 "
        "{%0,%1,%2,%3}, {%4,%5,%6,%7}, {%8,%9}, {%0,%1,%2,%3};"
        : "+f"(c[0]), "+f"(c[1]), "+f"(c[2]), "+f"(c[3])
        : "r"(a[0]), "r"(a[1]), "r"(a[2]), "r"(a[3]), "r"(b0), "r"(b1));
}

__device__ __forceinline__ void ldsm_x4(unsigned* r, unsigned addr) {
    asm volatile("ldmatrix.sync.aligned.m8n8.x4.shared.b16 {%0,%1,%2,%3}, [%4];"
                 : "=r"(r[0]), "=r"(r[1]), "=r"(r[2]), "=r"(r[3]) : "r"(addr));
}

__device__ __forceinline__ float lrelu(float e) { return e > 0.f ? e : 0.2f * e; }

// ---------------- CSR build ----------------
__global__ void k_zero() {
    int i = blockIdx.x * blockDim.x + threadIdx.x;
    if (i < NN) { g_cnt[i] = 0; g_es2[i] = 0.f; g_ed2[i] = 0.f; }
}

__global__ void k_count(const int* __restrict__ ei) {
    int t = blockIdx.x * blockDim.x + threadIdx.x;
    if (t >= ET) return;
    int dst = (t < NE) ? ei[NE + t] : (t - NE);
    atomicAdd(&g_cnt[dst], 1);
}

__global__ void k_scan1() {
    __shared__ int wsum[16];
    int t = threadIdx.x;
    int i = blockIdx.x * SCB + t;
    int v = (i < NN) ? g_cnt[i] : 0;
#pragma unroll
    for (int o = 16; o; o >>= 1) v += __shfl_xor_sync(0xFFFFFFFFu, v, o);
    if ((t & 31) == 0) wsum[t >> 5] = v;
    __syncthreads();
    if (t < 16) {
        int s = wsum[t];
#pragma unroll
        for (int o = 8; o; o >>= 1) s += __shfl_xor_sync(0xFFFFu, s, o);
        if (t == 0) g_bsum[blockIdx.x] = s;
    }
}

__global__ void k_scan2() {
    __shared__ int s[128];
    int t = threadIdx.x;
    int v = (t < NBL) ? g_bsum[t] : 0;
    s[t] = v;
    __syncthreads();
#pragma unroll
    for (int d = 1; d < 128; d <<= 1) {
        int u = (t >= d) ? s[t - d] : 0;
        __syncthreads();
        s[t] += u;
        __syncthreads();
    }
    if (t < NBL) g_bsum[t] = s[t] - v;   // exclusive
    if (t == 0) g_off[NN] = ET;
}

__global__ void k_scan3() {
    __shared__ int s[SCB];
    int t = threadIdx.x;
    int i = blockIdx.x * SCB + t;
    int v = (i < NN) ? g_cnt[i] : 0;
    s[t] = v;
    __syncthreads();
#pragma unroll
    for (int d = 1; d < SCB; d <<= 1) {
        int u = (t >= d) ? s[t - d] : 0;
        __syncthreads();
        s[t] += u;
        __syncthreads();
    }
    if (i < NN) {
        int e = s[t] - v + g_bsum[blockIdx.x];
        g_off[i] = e;
        g_cur[i] = e;
    }
}

__global__ void k_scatter(const int* __restrict__ ei) {
    int t = blockIdx.x * blockDim.x + threadIdx.x;
    if (t >= ET) return;
    int src, dst;
    if (t < NE) { src = ei[t]; dst = ei[NE + t]; }
    else        { src = t - NE; dst = t - NE; }
    int pos = atomicAdd(&g_cur[dst], 1);
    g_srcl[pos] = src;
}

// ---------------- weight prep: transpose + bf16 split ----------------
__global__ void k_prepB(const float* __restrict__ W1, const float* __restrict__ W2) {
    int t = blockIdx.x * blockDim.x + threadIdx.x;
    if (t < 256 * 128) {
        int n = t >> 7, k = t & 127;
        float v = W1[k * 256 + n];
        __nv_bfloat16 h = __float2bfloat16_rn(v);
        g_bt1h[n * 128 + k] = h;
        g_bt1l[n * 128 + k] = __float2bfloat16_rn(v - __bfloat162float(h));
    }
    int t2 = t - 256 * 128;
    if (t2 >= 0 && t2 < 256 * 256) {
        int n = t2 >> 8, k = t2 & 255;
        float v = W2[k * 256 + n];
        __nv_bfloat16 h = __float2bfloat16_rn(v);
        g_bt2h[n * 256 + k] = h;
        g_bt2l[n * 256 + k] = __float2bfloat16_rn(v - __bfloat162float(h));
    }
}

// ---------------- HMMA GEMM, double-buffered, ldmatrix frags, fused attn dots -------
#define SROW 40
#define BUFSZ 40960
#define PLANE 10240

template <int L>
__global__ __launch_bounds__(256)
void k_gemm_mma(const float* __restrict__ Ain,
                const float* __restrict__ asrc, const float* __restrict__ adst) {
    constexpr int KD = (L == 1) ? 128 : 256;
    constexpr int NCH = KD / 32;
    const float* A = (L == 1) ? Ain : g_act;
    float* Cc = (L == 1) ? g_h1 : g_h2;
    const __nv_bfloat16* Bh = (L == 1) ? g_bt1h : g_bt2h;
    const __nv_bfloat16* Bl = (L == 1) ? g_bt1l : g_bt2l;

    extern __shared__ char smem[];
    unsigned sbase = (unsigned)__cvta_generic_to_shared(smem);

    int tid = threadIdx.x, wid = tid >> 5, lane = tid & 31;
    int warpM = wid >> 1, warpN = wid & 1;       // 4 x 2 warp grid
    int row0 = blockIdx.y * 128, col0 = blockIdx.x * 128;

    int ar = tid >> 1, ahalf = tid & 1;
    int agr = row0 + ar;
    bool av = agr < NN;
    const float* arowb = A + (size_t)agr * KD + ahalf * 16;

    // ldmatrix lane geometry
    int g = lane >> 3, ri = lane & 7;
    int a_row = warpM * 32 + ((g & 1) ? 8 : 0) + ri;       // + mt*16 later
    int a_colx = (g & 2) ? 8 : 0;                          // + kt*16
    int b_row = warpN * 64 + ((g & 2) ? 8 : 0) + ri;       // + ntp*16
    int b_colx = (g & 1) ? 8 : 0;                          // + kt*16

    float acc[2][8][4];
#pragma unroll
    for (int mt = 0; mt < 2; mt++)
#pragma unroll
        for (int nt = 0; nt < 8; nt++)
#pragma unroll
            for (int q = 0; q < 4; q++) acc[mt][nt][q] = 0.f;

    float4 pa[4];
    uint4  pb[4];

    // ---- load + stage chunk 0 into buffer 0 ----
    {
        const float* p = arowb;
#pragma unroll
        for (int gg = 0; gg < 4; gg++)
            pa[gg] = av ? *(const float4*)(p + gg * 4) : make_float4(0.f, 0.f, 0.f, 0.f);
#pragma unroll
        for (int it = 0; it < 4; it++) {
            int seg = tid * 4 + it;
            int buf = seg >> 9, s = seg & 511;
            int n = s >> 2, sg = s & 3;
            const __nv_bfloat16* src = (buf ? Bl : Bh) + (size_t)(col0 + n) * KD + sg * 8;
            pb[it] = *(const uint4*)src;
        }
        uint4 hi4[2], lo4[2];
#pragma unroll
        for (int gg = 0; gg < 2; gg++) {
            float4 f0 = pa[gg * 2], f1 = pa[gg * 2 + 1];
            cvt2(f0.x, f0.y, hi4[gg].x, lo4[gg].x);
            cvt2(f0.z, f0.w, hi4[gg].y, lo4[gg].y);
            cvt2(f1.x, f1.y, hi4[gg].z, lo4[gg].z);
            cvt2(f1.z, f1.w, hi4[gg].w, lo4[gg].w);
        }
        char* dh = smem + ar * 80 + ahalf * 32;
        *(uint4*)(dh)              = hi4[0];
        *(uint4*)(dh + 16)         = hi4[1];
        *(uint4*)(dh + PLANE)      = lo4[0];
        *(uint4*)(dh + PLANE + 16) = lo4[1];
#pragma unroll
        for (int it = 0; it < 4; it++) {
            int seg = tid * 4 + it;
            int buf = seg >> 9, s = seg & 511;
            int n = s >> 2, sg = s & 3;
            *(uint4*)(smem + 20480 + buf * PLANE + n * 80 + sg * 16) = pb[it];
        }
    }
    __syncthreads();

    for (int ch = 0; ch < NCH; ch++) {
        // ---- prefetch next chunk's globals (latency covered by MMA below) ----
        if (ch + 1 < NCH) {
            const float* p = arowb + (ch + 1) * 32;
#pragma unroll
            for (int gg = 0; gg < 4; gg++)
                pa[gg] = av ? *(const float4*)(p + gg * 4) : make_float4(0.f, 0.f, 0.f, 0.f);
#pragma unroll
            for (int it = 0; it < 4; it++) {
                int seg = tid * 4 + it;
                int buf = seg >> 9, s = seg & 511;
                int n = s >> 2, sg = s & 3;
                const __nv_bfloat16* src = (buf ? Bl : Bh) + (size_t)(col0 + n) * KD + (ch + 1) * 32 + sg * 8;
                pb[it] = *(const uint4*)src;
            }
        }
        // ---- MMA on current buffer (ldmatrix fragment loads) ----
        {
            unsigned aHb = sbase + (unsigned)((ch & 1) * BUFSZ);
            unsigned aLb = aHb + PLANE;
            unsigned bHb = aHb + 20480;
            unsigned bLb = aHb + 30720;
#pragma unroll
            for (int kt = 0; kt < 2; kt++) {
                int acol = kt * 16 + a_colx;
                int bcol = kt * 16 + b_colx;
                unsigned aH[2][4], aL[2][4];
#pragma unroll
                for (int mt = 0; mt < 2; mt++) {
                    unsigned off = (unsigned)((a_row + mt * 16) * SROW + acol) * 2u;
                    ldsm_x4(aH[mt], aHb + off);
                    ldsm_x4(aL[mt], aLb + off);
                }
#pragma unroll
                for (int ntp = 0; ntp < 4; ntp++) {
                    unsigned off = (unsigned)((b_row + ntp * 16) * SROW + bcol) * 2u;
                    unsigned bH4[4], bL4[4];
                    ldsm_x4(bH4, bHb + off);
                    ldsm_x4(bL4, bLb + off);
#pragma unroll
                    for (int h = 0; h < 2; h++) {
                        int nt = ntp * 2 + h;
                        unsigned bH0 = bH4[h * 2], bH1 = bH4[h * 2 + 1];
                        unsigned bL0 = bL4[h * 2], bL1 = bL4[h * 2 + 1];
                        mma16816(acc[0][nt], aH[0], bH0, bH1);
                        mma16816(acc[1][nt], aH[1], bH0, bH1);
                        mma16816(acc[0][nt], aH[0], bL0, bL1);
                        mma16816(acc[1][nt], aH[1], bL0, bL1);
                        mma16816(acc[0][nt], aL[0], bH0, bH1);
                        mma16816(acc[1][nt], aL[1], bH0, bH1);
                    }
                }
            }
        }
        // ---- stage next chunk into the other buffer ----
        if (ch + 1 < NCH) {
            char* base = smem + ((ch + 1) & 1) * BUFSZ;
            uint4 hi4[2], lo4[2];
#pragma unroll
            for (int gg = 0; gg < 2; gg++) {
                float4 f0 = pa[gg * 2], f1 = pa[gg * 2 + 1];
                cvt2(f0.x, f0.y, hi4[gg].x, lo4[gg].x);
                cvt2(f0.z, f0.w, hi4[gg].y, lo4[gg].y);
                cvt2(f1.x, f1.y, hi4[gg].z, lo4[gg].z);
                cvt2(f1.z, f1.w, hi4[gg].w, lo4[gg].w);
            }
            char* dh = base + ar * 80 + ahalf * 32;
            *(uint4*)(dh)              = hi4[0];
            *(uint4*)(dh + 16)         = hi4[1];
            *(uint4*)(dh + PLANE)      = lo4[0];
            *(uint4*)(dh + PLANE + 16) = lo4[1];
#pragma unroll
            for (int it = 0; it < 4; it++) {
                int seg = tid * 4 + it;
                int buf = seg >> 9, s = seg & 511;
                int n = s >> 2, sg = s & 3;
                *(uint4*)(base + 20480 + buf * PLANE + n * 80 + sg * 16) = pb[it];
            }
        }
        __syncthreads();
    }

    // ---- epilogue: store C ----
#pragma unroll
    for (int mt = 0; mt < 2; mt++) {
        int r_lo = row0 + warpM * 32 + mt * 16 + (lane >> 2);
        int cc = col0 + warpN * 64 + (lane & 3) * 2;
#pragma unroll
        for (int nt = 0; nt < 8; nt++) {
            if (r_lo < NN)
                *(float2*)(Cc + (size_t)r_lo * DD + cc + nt * 8) =
                    make_float2(acc[mt][nt][0], acc[mt][nt][1]);
            if (r_lo + 8 < NN)
                *(float2*)(Cc + (size_t)(r_lo + 8) * DD + cc + nt * 8) =
                    make_float2(acc[mt][nt][2], acc[mt][nt][3]);
        }
    }

    // ---- fused attention coefficient dots ----
    if (L == 1) {
        float pes[2][2][2], ped[2][2][2];
#pragma unroll
        for (int a0 = 0; a0 < 2; a0++)
#pragma unroll
            for (int a1 = 0; a1 < 2; a1++)
#pragma unroll
                for (int a2 = 0; a2 < 2; a2++) { pes[a0][a1][a2] = 0.f; ped[a0][a1][a2] = 0.f; }
#pragma unroll
        for (int nt = 0; nt < 8; nt++) {
            int colg = col0 + warpN * 64 + nt * 8 + (lane & 3) * 2;
            float a0s = __ldg(asrc + colg), a1s = __ldg(asrc + colg + 1);
            float a0d = __ldg(adst + colg), a1d = __ldg(adst + colg + 1);
            int hb = nt >> 2;
#pragma unroll
            for (int mt = 0; mt < 2; mt++) {
                pes[mt][0][hb] += acc[mt][nt][0] * a0s + acc[mt][nt][1] * a1s;
                pes[mt][1][hb] += acc[mt][nt][2] * a0s + acc[mt][nt][3] * a1s;
                ped[mt][0][hb] += acc[mt][nt][0] * a0d + acc[mt][nt][1] * a1d;
                ped[mt][1][hb] += acc[mt][nt][2] * a0d + acc[mt][nt][3] * a1d;
            }
        }
#pragma unroll
        for (int a0 = 0; a0 < 2; a0++)
#pragma unroll
            for (int a1 = 0; a1 < 2; a1++)
#pragma unroll
                for (int a2 = 0; a2 < 2; a2++) {
                    pes[a0][a1][a2] += __shfl_xor_sync(0xFFFFFFFFu, pes[a0][a1][a2], 1);
                    pes[a0][a1][a2] += __shfl_xor_sync(0xFFFFFFFFu, pes[a0][a1][a2], 2);
                    ped[a0][a1][a2] += __shfl_xor_sync(0xFFFFFFFFu, ped[a0][a1][a2], 1);
                    ped[a0][a1][a2] += __shfl_xor_sync(0xFFFFFFFFu, ped[a0][a1][a2], 2);
                }
        if ((lane & 3) == 0) {
#pragma unroll
            for (int mt = 0; mt < 2; mt++)
#pragma unroll
                for (int rs = 0; rs < 2; rs++) {
                    int node = row0 + warpM * 32 + mt * 16 + (lane >> 2) + rs * 8;
                    if (node < NN) {
#pragma unroll
                        for (int hb = 0; hb < 2; hb++) {
                            int head = blockIdx.x * 4 + warpN * 2 + hb;
                            g_es1[node * 8 + head] = pes[mt][rs][hb];
                            g_ed1[node * 8 + head] = ped[mt][rs][hb];
                        }
                    }
                }
        }
    } else {
        float pes[2][2], ped[2][2];
#pragma unroll
        for (int a0 = 0; a0 < 2; a0++)
#pragma unroll
            for (int a1 = 0; a1 < 2; a1++) { pes[a0][a1] = 0.f; ped[a0][a1] = 0.f; }
#pragma unroll
        for (int nt = 0; nt < 8; nt++) {
            int colg = col0 + warpN * 64 + nt * 8 + (lane & 3) * 2;
            float a0s = __ldg(asrc + colg), a1s = __ldg(asrc + colg + 1);
            float a0d = __ldg(adst + colg), a1d = __ldg(adst + colg + 1);
#pragma unroll
            for (int mt = 0; mt < 2; mt++) {
                pes[mt][0] += acc[mt][nt][0] * a0s + acc[mt][nt][1] * a1s;
                pes[mt][1] += acc[mt][nt][2] * a0s + acc[mt][nt][3] * a1s;
                ped[mt][0] += acc[mt][nt][0] * a0d + acc[mt][nt][1] * a1d;
                ped[mt][1] += acc[mt][nt][2] * a0d + acc[mt][nt][3] * a1d;
            }
        }
#pragma unroll
        for (int a0 = 0; a0 < 2; a0++)
#pragma unroll
            for (int a1 = 0; a1 < 2; a1++) {
                pes[a0][a1] += __shfl_xor_sync(0xFFFFFFFFu, pes[a0][a1], 1);
                pes[a0][a1] += __shfl_xor_sync(0xFFFFFFFFu, pes[a0][a1], 2);
                ped[a0][a1] += __shfl_xor_sync(0xFFFFFFFFu, ped[a0][a1], 1);
                ped[a0][a1] += __shfl_xor_sync(0xFFFFFFFFu, ped[a0][a1], 2);
            }
        if ((lane & 3) == 0) {
#pragma unroll
            for (int mt = 0; mt < 2; mt++)
#pragma unroll
                for (int rs = 0; rs < 2; rs++) {
                    int node = row0 + warpM * 32 + mt * 16 + (lane >> 2) + rs * 8;
                    if (node < NN) {
                        atomicAdd(&g_es2[node], pes[mt][rs]);
                        atomicAdd(&g_ed2[node], ped[mt][rs]);
                    }
                }
        }
    }
}

// ---------------- GAT layer 1: warp per dst node; lane owns 8 cols of one head -------
// exp computed in-place (no precomputed w buffer)
__global__ void k_gat1(const float* __restrict__ b1) {
    int n = (blockIdx.x * blockDim.x + threadIdx.x) >> 5;
    int lane = threadIdx.x & 31;
    if (n >= NN) return;
    int beg = g_off[n], end = g_off[n + 1];
    int col = lane * 8;           // cols [col, col+8) all in head lane>>2
    int head = lane >> 2;

    float ed_h = g_ed1[n * HH + head];

    float s = 0.f;
    float acc[8];
#pragma unroll
    for (int q = 0; q < 8; q++) acc[q] = 0.f;

#pragma unroll 8
    for (int i = beg; i < end; i++) {
        int sc = g_srcl[i];
        float w = __expf(lrelu(g_es1[sc * HH + head] + ed_h));
        const float* hrow = g_h1 + (size_t)sc * DD + col;
        float4 h0 = *(const float4*)(hrow);
        float4 h1 = *(const float4*)(hrow + 4);
        s += w;
        acc[0] = fmaf(w, h0.x, acc[0]);
        acc[1] = fmaf(w, h0.y, acc[1]);
        acc[2] = fmaf(w, h0.z, acc[2]);
        acc[3] = fmaf(w, h0.w, acc[3]);
        acc[4] = fmaf(w, h1.x, acc[4]);
        acc[5] = fmaf(w, h1.y, acc[5]);
        acc[6] = fmaf(w, h1.z, acc[6]);
        acc[7] = fmaf(w, h1.w, acc[7]);
    }
    float inv = 1.f / (s + 1e-16f);
    float res[8];
#pragma unroll
    for (int q = 0; q < 8; q++) {
        float v = acc[q] * inv + b1[col + q];
        res[q] = v > 0.f ? v : expm1f(v);  // ELU
    }
    float4 o0 = make_float4(res[0], res[1], res[2], res[3]);
    float4 o1 = make_float4(res[4], res[5], res[6], res[7]);
    float* dst = g_act + (size_t)n * DD + col;
    *(float4*)(dst)     = o0;
    *(float4*)(dst + 4) = o1;
}

// ---------------- GAT layer 2 (H=1, C=256): warp per dst node, lane owns 8 cols ------
__global__ void k_gat2(const float* __restrict__ b2, float* __restrict__ out) {
    int n = (blockIdx.x * blockDim.x + threadIdx.x) >> 5;
    int lane = threadIdx.x & 31;
    if (n >= NN) return;
    int beg = g_off[n], end = g_off[n + 1];
    int col = lane * 8;

    float ed = g_ed2[n];

    float s = 0.f;
    float acc[8];
#pragma unroll
    for (int q = 0; q < 8; q++) acc[q] = 0.f;

#pragma unroll 8
    for (int i = beg; i < end; i++) {
        int sc = g_srcl[i];
        float w = __expf(lrelu(g_es2[sc] + ed));
        const float* hrow = g_h2 + (size_t)sc * DD + col;
        float4 h0 = *(const float4*)(hrow);
        float4 h1 = *(const float4*)(hrow + 4);
        s += w;
        acc[0] = fmaf(w, h0.x, acc[0]);
        acc[1] = fmaf(w, h0.y, acc[1]);
        acc[2] = fmaf(w, h0.z, acc[2]);
        acc[3] = fmaf(w, h0.w, acc[3]);
        acc[4] = fmaf(w, h1.x, acc[4]);
        acc[5] = fmaf(w, h1.y, acc[5]);
        acc[6] = fmaf(w, h1.z, acc[6]);
        acc[7] = fmaf(w, h1.w, acc[7]);
    }
    float inv = 1.f / (s + 1e-16f);
    float4 o0 = make_float4(acc[0] * inv + b2[col],     acc[1] * inv + b2[col + 1],
                            acc[2] * inv + b2[col + 2], acc[3] * inv + b2[col + 3]);
    float4 o1 = make_float4(acc[4] * inv + b2[col + 4], acc[5] * inv + b2[col + 5],
                            acc[6] * inv + b2[col + 6], acc[7] * inv + b2[col + 7]);
    float* dst = out + (size_t)n * DD + col;
    *(float4*)(dst)     = o0;
    *(float4*)(dst + 4) = o1;
}

// ---------------- launch ----------------
#define SMEM_GEMM 81920

extern "C" void kernel_launch(void* const* d_in, const int* in_sizes, int n_in,
                              void* d_out, int out_size) {
    const float* x      = (const float*)d_in[0];
    const int*   ei     = (const int*)d_in[1];
    const float* W1     = (const float*)d_in[2];
    const float* a_src1 = (const float*)d_in[3];
    const float* a_dst1 = (const float*)d_in[4];
    const float* b1     = (const float*)d_in[5];
    const float* W2     = (const float*)d_in[6];
    const float* a_src2 = (const float*)d_in[7];
    const float* a_dst2 = (const float*)d_in[8];
    const float* b2     = (const float*)d_in[9];
    float* out = (float*)d_out;

    cudaFuncSetAttribute(k_gemm_mma<1>, cudaFuncAttributeMaxDynamicSharedMemorySize, SMEM_GEMM);
    cudaFuncSetAttribute(k_gemm_mma<2>, cudaFuncAttributeMaxDynamicSharedMemorySize, SMEM_GEMM);

    dim3 gdim(2, (NN + 127) / 128);
    int warp_grid = (NN * 32 + 255) / 256;

    cudaStream_t s0 = (cudaStream_t)0;

    // fork-join: CSR build on side stream, prepB+GEMM1 on main stream
    cudaStream_t s1 = 0;
    cudaEvent_t ef = 0, ej = 0;
    bool fork = (cudaStreamCreateWithFlags(&s1, cudaStreamNonBlocking) == cudaSuccess) &&
                (cudaEventCreateWithFlags(&ef, cudaEventDisableTiming) == cudaSuccess) &&
                (cudaEventCreateWithFlags(&ej, cudaEventDisableTiming) == cudaSuccess);

    cudaStream_t sc = fork ? s1 : s0;
    if (fork) {
        cudaEventRecord(ef, s0);
        cudaStreamWaitEvent(s1, ef, 0);
    }

    // CSR chain (side stream when forked)
    k_zero<<<(NN + 255) / 256, 256, 0, sc>>>();
    k_count<<<(ET + 255) / 256, 256, 0, sc>>>(ei);
    k_scan1<<<NBL, SCB, 0, sc>>>();
    k_scan2<<<1, 128, 0, sc>>>();
    k_scan3<<<NBL, SCB, 0, sc>>>();
    k_scatter<<<(ET + 255) / 256, 256, 0, sc>>>(ei);
    if (fork) cudaEventRecord(ej, s1);

    // main chain: weight prep + GEMM1 (independent of CSR)
    k_prepB<<<(256 * 128 + 256 * 256 + 255) / 256, 256, 0, s0>>>(W1, W2);
    k_gemm_mma<1><<<gdim, 256, SMEM_GEMM, s0>>>(x, a_src1, a_dst1);

    if (fork) cudaStreamWaitEvent(s0, ej, 0);

    // layer1 aggregate (exp fused in)
    k_gat1<<<warp_grid, 256, 0, s0>>>(b1);

    // layer 2
    k_gemm_mma<2><<<gdim, 256, SMEM_GEMM, s0>>>(nullptr, a_src2, a_dst2);
    k_gat2<<<warp_grid, 256, 0, s0>>>(b2, out);

    // cleanup only when not capturing (capture call leaks 1 stream + 2 events, once)
    cudaStreamCaptureStatus cs = cudaStreamCaptureStatusNone;
    cudaStreamIsCapturing(s0, &cs);
    if (fork && cs == cudaStreamCaptureStatusNone) {
        cudaStreamDestroy(s1);
        cudaEventDestroy(ef);
        cudaEventDestroy(ej);
    }
}